// round 12
// baseline (speedup 1.0000x reference)
#include <cuda_runtime.h>
#include <cuda_fp16.h>
#include <cstdint>

// Problem constants
static constexpr int B_ = 4;
static constexpr int C_ = 256;
static constexpr int N_ = 32768;     // 32*32*32
static constexpr int H_ = 8;
static constexpr int NCH = 128;      // n-chunks of 256

// ---------------- device scratch (no allocations allowed) ----------------
__device__ __half d_xT[(long)B_ * N_ * C_];        // xT [b][n][c] fp16
__device__ __half d_Wp[B_ * 768 * C_];             // GN-folded qkv weight fp16
__device__ float d_biasp[B_ * 768];
__device__ float d_W2f[B_ * C_ * C_];              // sim-fused out weight fp32
__device__ __half d_W3[B_ * C_ * C_];              // W2 @ Wq' fp16
__device__ float d_bias3[B_ * C_];
__device__ float2 d_gpart[16 * 1024];              // GN partials (sum, sumsq)
__device__ float d_scale[B_ * C_];
__device__ float d_shift[B_ * C_];
__device__ float d_cm[(long)B_ * H_ * NCH * 32];   // per-chunk k row max
__device__ float d_cs[(long)B_ * H_ * NCH * 32];   // per-chunk sumexp
__device__ float d_simpart[(long)B_ * H_ * NCH * 1024];
__device__ float d_sim[B_ * H_ * 1024];

// ---------------- PTX helpers ----------------
__device__ __forceinline__ uint32_t smem_u32(const void* p) {
    uint32_t a;
    asm("{ .reg .u64 t; cvta.to.shared.u64 t, %1; cvt.u32.u64 %0, t; }" : "=r"(a) : "l"(p));
    return a;
}
#define CP16(dst, src) asm volatile("cp.async.cg.shared.global [%0], [%1], 16;" :: "r"(dst), "l"(src))
#define CP_COMMIT()    asm volatile("cp.async.commit_group;")

__device__ __forceinline__ void ldm4(uint32_t* r, uint32_t addr) {
    asm volatile("ldmatrix.sync.aligned.m8n8.x4.shared.b16 {%0,%1,%2,%3}, [%4];"
        : "=r"(r[0]), "=r"(r[1]), "=r"(r[2]), "=r"(r[3]) : "r"(addr));
}
__device__ __forceinline__ void mma_f16(float* d, const uint32_t* a, const uint32_t* b) {
    asm volatile(
        "mma.sync.aligned.m16n8k16.row.col.f32.f16.f16.f32 "
        "{%0,%1,%2,%3}, {%4,%5,%6,%7}, {%8,%9}, {%0,%1,%2,%3};"
        : "+f"(d[0]), "+f"(d[1]), "+f"(d[2]), "+f"(d[3])
        : "r"(a[0]), "r"(a[1]), "r"(a[2]), "r"(a[3]), "r"(b[0]), "r"(b[1]));
}

// ============================================================
// Fused: x transpose->fp16 xT + GN partial stats.
// ============================================================
__global__ void tconv_stats(const float* __restrict__ x, __half* __restrict__ dst) {
    __shared__ float t[64][33];
    __shared__ float rs[256], rss[256];
    int n0 = blockIdx.x * 32, c0 = blockIdx.y * 64, b = blockIdx.z;
    const float* s = x + (long)b * C_ * N_;
    int tx = threadIdx.x, ty = threadIdx.y;
    int tid = ty * 32 + tx;
    float sum = 0.f, ss = 0.f;
    #pragma unroll
    for (int i = 0; i < 8; i++) {
        int cl = ty + i * 8;
        float v = s[(long)(c0 + cl) * N_ + n0 + tx];
        t[cl][tx] = v;
        sum += v; ss += v * v;
    }
    rs[tid] = sum; rss[tid] = ss;
    __syncthreads();
    __half* ph = dst + (long)b * N_ * C_;
    #pragma unroll
    for (int i = 0; i < 4; i++) {
        int nl = ty + i * 8;
        __half2 h = __floats2half2_rn(t[2 * tx][nl], t[2 * tx + 1][nl]);
        *(__half2*)&ph[(long)(n0 + nl) * C_ + c0 + 2 * tx] = h;
    }
    for (int st = 128; st > 0; st >>= 1) {
        if (tid < st) { rs[tid] += rs[tid + st]; rss[tid] += rss[tid + st]; }
        __syncthreads();
    }
    if (tid == 0)
        d_gpart[(b * 4 + blockIdx.y) * 1024 + blockIdx.x] = make_float2(rs[0], rss[0]);
}

__global__ void gn_stats2(const float* __restrict__ gnw, const float* __restrict__ gnb) {
    int bg = blockIdx.x, tid = threadIdx.x;
    __shared__ float rs[256], rss[256];
    float s = 0.f, ss = 0.f;
    for (int i = tid; i < 1024; i += 256) {
        float2 p = d_gpart[bg * 1024 + i];
        s += p.x; ss += p.y;
    }
    rs[tid] = s; rss[tid] = ss;
    __syncthreads();
    for (int st = 128; st > 0; st >>= 1) {
        if (tid < st) { rs[tid] += rs[tid + st]; rss[tid] += rss[tid + st]; }
        __syncthreads();
    }
    if (tid < 64) {
        float inv = 1.0f / (float)(64L * N_);
        float mean = rs[0] * inv;
        float var = rss[0] * inv - mean * mean;
        float rstd = rsqrtf(var + 1e-5f);
        int b = bg >> 2, g = bg & 3;
        int c = g * 64 + tid;
        float sc = rstd * gnw[c];
        d_scale[b * C_ + c] = sc;
        d_shift[b * C_ + c] = gnb[c] - mean * sc;
    }
}

__global__ void build_wp(const float* __restrict__ W) {
    int o = blockIdx.x, b = blockIdx.y, c = threadIdx.x;
    float w = W[o * C_ + c];
    d_Wp[((long)b * 768 + o) * C_ + c] = __float2half_rn(w * d_scale[b * C_ + c]);
    __shared__ float red[256];
    red[c] = w * d_shift[b * C_ + c];
    __syncthreads();
    for (int st = 128; st > 0; st >>= 1) {
        if (c < st) red[c] += red[c + st];
        __syncthreads();
    }
    if (c == 0) d_biasp[b * 768 + o] = red[0];
}

// ============================================================
// kv_sim: fused k/v GEMM + per-chunk softmax stats + sim partial.
// grid (h=8, nt=128, b=4), block 256 (8 warps).
// Phase 1: [k(32); v(32)] (M=64) x xT-chunk (N=256) over K=256, BK=32, 4-stage.
// Phase 2: expk(32xN) @ v(32xN)^T via HMMA -> simpart + (m,s) stats.
// ============================================================
static constexpr int KV_AROW = 80;                 // bytes per smem row (32+8 halves)
static constexpr int KV_ATILE = 64 * KV_AROW;      // 5120
static constexpr int KV_BTILE = 256 * KV_AROW;     // 20480
static constexpr int KV_STAGE = KV_ATILE + KV_BTILE;  // 25600
static constexpr int KV_SMEM = 4 * KV_STAGE;       // 102400
static constexpr int XROW = 528;                   // 264 halves per kx/vx row

__global__ void __launch_bounds__(256, 2) kv_sim() {
    extern __shared__ char smem[];
    uint32_t sb = smem_u32(smem);
    int tid = threadIdx.x, lane = tid & 31, wrp = tid >> 5;
    int h = blockIdx.x, nt = blockIdx.y, b = blockIdx.z;
    int wn = wrp * 32;

    const __half* Ak = d_Wp + ((long)b * 768 + 256 + h * 32) * 256;
    const __half* Av = d_Wp + ((long)b * 768 + 512 + h * 32) * 256;
    const __half* Bx = d_xT + ((long)b * N_ + nt * 256) * 256;

    float acc[4][4][4];
    #pragma unroll
    for (int i = 0; i < 4; i++)
        #pragma unroll
        for (int j = 0; j < 4; j++)
            #pragma unroll
            for (int e = 0; e < 4; e++) acc[i][j][e] = 0.f;

    auto load_st = [&](int kt) {
        uint32_t sbase = sb + (kt & 3) * KV_STAGE;
        int k0 = kt * 32;
        {   // A: 64 rows x 4 segs, 1 per thread
            int row = tid >> 2, seg = tid & 3;
            const __half* src = (row < 32 ? Ak + (long)row * 256
                                          : Av + (long)(row - 32) * 256) + k0 + seg * 8;
            CP16(sbase + row * KV_AROW + seg * 16, src);
        }
        #pragma unroll
        for (int it = 0; it < 4; it++) {   // B: 256 rows x 4 segs
            int idx = tid + it * 256;
            int row = idx >> 2, seg = idx & 3;
            CP16(sbase + KV_ATILE + row * KV_AROW + seg * 16,
                 Bx + (long)row * 256 + k0 + seg * 8);
        }
        CP_COMMIT();
    };

    load_st(0); load_st(1); load_st(2);

    int quad = lane >> 3, qr = lane & 7;
    int a_row = (quad & 1) * 8 + qr;
    int a_cb = (quad >> 1) * 16;
    int b_row = wn + ((lane >> 4) & 1) * 8 + (lane & 7);
    int b_cb = ((lane >> 3) & 1) * 16;

    #pragma unroll 1
    for (int kt = 0; kt < 8; kt++) {
        if (kt < 6)      { asm volatile("cp.async.wait_group 2;"); }
        else if (kt == 6){ asm volatile("cp.async.wait_group 1;"); }
        else             { asm volatile("cp.async.wait_group 0;"); }
        __syncthreads();
        if (kt + 3 < 8) load_st(kt + 3);

        uint32_t base = sb + (kt & 3) * KV_STAGE;
        uint32_t aS = base, bS = base + KV_ATILE;
        #pragma unroll
        for (int k16 = 0; k16 < 2; k16++) {
            uint32_t acol = a_cb + k16 * 32;
            uint32_t bcol = b_cb + k16 * 32;
            uint32_t ah[4][4], bh[4][2];
            #pragma unroll
            for (int mf = 0; mf < 4; mf++)
                ldm4(ah[mf], aS + (a_row + mf * 16) * KV_AROW + acol);
            #pragma unroll
            for (int nfp = 0; nfp < 2; nfp++) {
                uint32_t r4[4];
                ldm4(r4, bS + (b_row + nfp * 16) * KV_AROW + bcol);
                bh[nfp * 2 + 0][0] = r4[0]; bh[nfp * 2 + 0][1] = r4[1];
                bh[nfp * 2 + 1][0] = r4[2]; bh[nfp * 2 + 1][1] = r4[3];
            }
            #pragma unroll
            for (int mf = 0; mf < 4; mf++)
                #pragma unroll
                for (int nf = 0; nf < 4; nf++)
                    mma_f16(acc[mf][nf], ah[mf], bh[nf]);
        }
    }
    __syncthreads();   // GEMM done; smem reused below

    // ---- overlay layout ----
    char* kx = smem;                       // 32 x 528 B
    char* vx = smem + 16896;               // 32 x 528 B
    float* red = (float*)(smem + 33792);   // 8 x 1024 floats
    float* sm_m = (float*)(smem + 66560);  // [32][8]
    float* sm_s = (float*)(smem + 67584);  // [32][8]
    float* gm   = (float*)(smem + 68608);  // [32]

    long bhc = ((long)(b * H_ + h) * NCH + nt);
    const float* bp = d_biasp + b * 768;

    // pass A: v -> vx fp16; k -> per-warp row max
    #pragma unroll
    for (int mf = 0; mf < 4; mf++) {
        #pragma unroll
        for (int hf = 0; hf < 2; hf++) {
            int r = mf * 16 + hf * 8 + (lane >> 2);
            if (mf < 2) {
                float bv = bp[256 + h * 32 + r];
                float mx = -1e30f;
                #pragma unroll
                for (int nf = 0; nf < 4; nf++) {
                    mx = fmaxf(mx, acc[mf][nf][hf * 2] + bv);
                    mx = fmaxf(mx, acc[mf][nf][hf * 2 + 1] + bv);
                }
                mx = fmaxf(mx, __shfl_xor_sync(0xffffffffu, mx, 1));
                mx = fmaxf(mx, __shfl_xor_sync(0xffffffffu, mx, 2));
                if ((lane & 3) == 0) sm_m[r * 8 + wrp] = mx;
            } else {
                int e = r - 32;
                float bv = bp[512 + h * 32 + e];
                #pragma unroll
                for (int nf = 0; nf < 4; nf++) {
                    int c = wn + nf * 8 + 2 * (lane & 3);
                    *(__half2*)(vx + e * XROW + c * 2) =
                        __floats2half2_rn(acc[mf][nf][hf * 2] + bv,
                                          acc[mf][nf][hf * 2 + 1] + bv);
                }
            }
        }
    }
    __syncthreads();
    if (tid < 32) {
        float mx = sm_m[tid * 8];
        #pragma unroll
        for (int ww = 1; ww < 8; ww++) mx = fmaxf(mx, sm_m[tid * 8 + ww]);
        gm[tid] = mx;
    }
    __syncthreads();

    // pass B: expk -> kx fp16 + per-warp sumexp
    #pragma unroll
    for (int mf = 0; mf < 2; mf++) {
        #pragma unroll
        for (int hf = 0; hf < 2; hf++) {
            int r = mf * 16 + hf * 8 + (lane >> 2);
            float bv = bp[256 + h * 32 + r];
            float m = gm[r];
            float ssum = 0.f;
            #pragma unroll
            for (int nf = 0; nf < 4; nf++) {
                int c = wn + nf * 8 + 2 * (lane & 3);
                float e0 = __expf(acc[mf][nf][hf * 2] + bv - m);
                float e1 = __expf(acc[mf][nf][hf * 2 + 1] + bv - m);
                ssum += e0 + e1;
                *(__half2*)(kx + r * XROW + c * 2) = __floats2half2_rn(e0, e1);
            }
            ssum += __shfl_xor_sync(0xffffffffu, ssum, 1);
            ssum += __shfl_xor_sync(0xffffffffu, ssum, 2);
            if ((lane & 3) == 0) sm_s[r * 8 + wrp] = ssum;
        }
    }
    __syncthreads();
    if (tid < 32) {
        float s = 0.f;
        #pragma unroll
        for (int ww = 0; ww < 8; ww++) s += sm_s[tid * 8 + ww];
        d_cm[bhc * 32 + tid] = gm[tid];
        d_cs[bhc * 32 + tid] = s;
    }

    // phase 2: simpart = expk(32x256) @ v(32x256)^T, warp = 32-wide K slice
    float acc2[2][4][4];
    #pragma unroll
    for (int i = 0; i < 2; i++)
        #pragma unroll
        for (int j = 0; j < 4; j++)
            #pragma unroll
            for (int e = 0; e < 4; e++) acc2[i][j][e] = 0.f;

    uint32_t kxu = smem_u32(kx), vxu = smem_u32(vx);
    int a2_row = (quad & 1) * 8 + qr;
    int b2_row = ((lane >> 4) & 1) * 8 + (lane & 7);
    uint32_t colb = wrp * 64;
    #pragma unroll
    for (int k16 = 0; k16 < 2; k16++) {
        uint32_t ac = colb + k16 * 32 + a_cb;
        uint32_t bc = colb + k16 * 32 + b_cb;
        uint32_t af[2][4], bf[4][2];
        #pragma unroll
        for (int mf = 0; mf < 2; mf++)
            ldm4(af[mf], kxu + (a2_row + mf * 16) * XROW + ac);
        #pragma unroll
        for (int nfp = 0; nfp < 2; nfp++) {
            uint32_t r4[4];
            ldm4(r4, vxu + (b2_row + nfp * 16) * XROW + bc);
            bf[nfp * 2 + 0][0] = r4[0]; bf[nfp * 2 + 0][1] = r4[1];
            bf[nfp * 2 + 1][0] = r4[2]; bf[nfp * 2 + 1][1] = r4[3];
        }
        #pragma unroll
        for (int mf = 0; mf < 2; mf++)
            #pragma unroll
            for (int nf = 0; nf < 4; nf++)
                mma_f16(acc2[mf][nf], af[mf], bf[nf]);
    }

    float* my = red + wrp * 1024;
    #pragma unroll
    for (int mf = 0; mf < 2; mf++) {
        int r = mf * 16 + (lane >> 2);
        #pragma unroll
        for (int nf = 0; nf < 4; nf++) {
            int c = nf * 8 + 2 * (lane & 3);
            my[r * 32 + c]           = acc2[mf][nf][0];
            my[r * 32 + c + 1]       = acc2[mf][nf][1];
            my[(r + 8) * 32 + c]     = acc2[mf][nf][2];
            my[(r + 8) * 32 + c + 1] = acc2[mf][nf][3];
        }
    }
    __syncthreads();
    float* outp = d_simpart + bhc * 1024;
    for (int i = tid; i < 1024; i += 256) {
        float s = 0.f;
        #pragma unroll
        for (int ww = 0; ww < 8; ww++) s += red[ww * 1024 + i];
        outp[i] = s;
    }
}

// ============================================================
// sim_reduce: merge 128 chunks with max-rescaling, divide by S.
// grid 32 (bh), block 1024.
// ============================================================
__global__ void sim_reduce() {
    __shared__ float m_s[4096], s_s[4096];
    int bh = blockIdx.x, i = threadIdx.x;
    int d = i >> 5;
    for (int idx = i; idx < 4096; idx += 1024) {
        m_s[idx] = d_cm[(long)bh * 4096 + idx];
        s_s[idx] = d_cs[(long)bh * 4096 + idx];
    }
    __syncthreads();
    float M = -1e30f;
    #pragma unroll 4
    for (int ch = 0; ch < NCH; ch++) M = fmaxf(M, m_s[ch * 32 + d]);
    float acc = 0.f, S = 0.f;
    const float* base = d_simpart + (long)bh * NCH * 1024;
    #pragma unroll 2
    for (int ch = 0; ch < NCH; ch++) {
        float w = __expf(m_s[ch * 32 + d] - M);
        acc += w * base[(long)ch * 1024 + i];
        S += w * s_s[ch * 32 + d];
    }
    d_sim[bh * 1024 + i] = acc / S;
}

// ============================================================
// W2f[b,o,h*32+d] = sum_e OW[o,h*32+e]*sim[b,h,d,e]  (fp32)
// ============================================================
__global__ void build_w2(const float* __restrict__ OW) {
    int o = blockIdx.x, b = blockIdx.y, cp = threadIdx.x;
    int h = cp >> 5, d = cp & 31;
    const float* simp = d_sim + ((long)((b * 8 + h) * 32 + d)) * 32;
    const float* owp = OW + o * C_ + h * 32;
    float s = 0.f;
    #pragma unroll
    for (int e = 0; e < 32; e++) s += owp[e] * simp[e];
    d_W2f[((long)b * C_ + o) * C_ + cp] = s;
}

// ============================================================
// W3[b] = W2f[b] @ Wq'[b] (fp16 out), bias3[b] = ob + W2f[b] @ bq'
// ============================================================
__global__ void build_w3(const float* __restrict__ ob) {
    int o = blockIdx.x, b = blockIdx.y, c = threadIdx.x;
    __shared__ float w2row[256];
    __shared__ float red[256];
    const float* w2p = d_W2f + ((long)b * C_ + o) * C_;
    w2row[c] = w2p[c];
    red[c] = w2row[c] * d_biasp[b * 768 + c];
    __syncthreads();
    float acc = 0.f;
    const __half* wq = d_Wp + (long)b * 768 * C_;
    #pragma unroll 8
    for (int e = 0; e < 256; e++)
        acc += w2row[e] * __half2float(wq[(long)e * C_ + c]);
    d_W3[((long)b * C_ + o) * C_ + c] = __float2half_rn(acc);
    for (int st = 128; st > 0; st >>= 1) {
        if (c < st) red[c] += red[c + st];
        __syncthreads();
    }
    if (c == 0) d_bias3[b * C_ + o] = ob[o] + red[0];
}

// ============================================================
// out GEMM: out = W3 @ xT^T + bias3 + x. BK=64, 3-stage.
// ============================================================
static constexpr int SKROW = 72;
static constexpr int TILE_BYTES = 128 * SKROW * 2;   // 18432
static constexpr int STAGE_BYTES = 2 * TILE_BYTES;   // 36864
static constexpr int GEMM_SMEM = 3 * STAGE_BYTES;    // 110592

__device__ __forceinline__ void load_stage(
    uint32_t sbase, const __half* A, const __half* Bm, int kt, int tid)
{
    int k0 = kt * 64;
    #pragma unroll
    for (int it = 0; it < 4; it++) {
        int i = tid + it * 256;
        int row = i >> 3, seg = i & 7;
        uint32_t doff = row * (SKROW * 2) + seg * 16;
        long goff = (long)row * 256 + k0 + seg * 8;
        CP16(sbase + doff,              A + goff);
        CP16(sbase + TILE_BYTES + doff, Bm + goff);
    }
}

__global__ void __launch_bounds__(256, 2) gemm_out(
    const __half* __restrict__ Amat, const __half* __restrict__ Bmat,
    const float* __restrict__ bias, const float* __restrict__ resid,
    float* __restrict__ outO)
{
    extern __shared__ char smem[];
    uint32_t sb = smem_u32(smem);
    int tid = threadIdx.x;
    int warp = tid >> 5, lane = tid & 31;
    int wm = (warp >> 2) * 64;
    int wn = (warp & 3) * 32;
    int mt = blockIdx.x, nt = blockIdx.y, b = blockIdx.z;

    const __half* A = Amat + (long)b * 256 * 256 + (long)mt * 128 * 256;
    const __half* Bm = Bmat + (long)b * N_ * 256 + (long)nt * 128 * 256;

    float acc[4][4][4];
    #pragma unroll
    for (int i = 0; i < 4; i++)
        #pragma unroll
        for (int j = 0; j < 4; j++)
            #pragma unroll
            for (int e = 0; e < 4; e++) acc[i][j][e] = 0.f;

    load_stage(sb + 0 * STAGE_BYTES, A, Bm, 0, tid); CP_COMMIT();
    load_stage(sb + 1 * STAGE_BYTES, A, Bm, 1, tid); CP_COMMIT();

    int quad = lane >> 3, qr = lane & 7;
    int a_row = wm + (quad & 1) * 8 + qr;
    int a_colb = (quad >> 1) * 16;
    int b_row = wn + ((lane >> 4) & 1) * 8 + (lane & 7);
    int b_colb = ((lane >> 3) & 1) * 16;

    #pragma unroll 1
    for (int kt = 0; kt < 4; kt++) {
        if (kt + 1 < 4) { asm volatile("cp.async.wait_group 1;"); }
        else            { asm volatile("cp.async.wait_group 0;"); }
        __syncthreads();
        if (kt + 2 < 4) {
            load_stage(sb + ((kt + 2) % 3) * STAGE_BYTES, A, Bm, kt + 2, tid);
            CP_COMMIT();
        }
        uint32_t base = sb + (kt % 3) * STAGE_BYTES;
        uint32_t aS = base, bS = base + TILE_BYTES;
        #pragma unroll
        for (int k16 = 0; k16 < 4; k16++) {
            uint32_t acol = a_colb + k16 * 32;
            uint32_t bcol = b_colb + k16 * 32;
            uint32_t ah[4][4], bh[4][2];
            #pragma unroll
            for (int mf = 0; mf < 4; mf++)
                ldm4(ah[mf], aS + (a_row + mf * 16) * (SKROW * 2) + acol);
            #pragma unroll
            for (int nfp = 0; nfp < 2; nfp++) {
                uint32_t r4[4];
                ldm4(r4, bS + (b_row + nfp * 16) * (SKROW * 2) + bcol);
                bh[nfp * 2 + 0][0] = r4[0]; bh[nfp * 2 + 0][1] = r4[1];
                bh[nfp * 2 + 1][0] = r4[2]; bh[nfp * 2 + 1][1] = r4[3];
            }
            #pragma unroll
            for (int mf = 0; mf < 4; mf++)
                #pragma unroll
                for (int nf = 0; nf < 4; nf++)
                    mma_f16(acc[mf][nf], ah[mf], bh[nf]);
        }
    }

    #pragma unroll
    for (int mf = 0; mf < 4; mf++) {
        #pragma unroll
        for (int hf = 0; hf < 2; hf++) {
            int mrow = mt * 128 + wm + mf * 16 + hf * 8 + (lane >> 2);
            float bv = bias[b * C_ + mrow];
            long base = ((long)b * C_ + mrow) * N_;
            float* dst = outO + base;
            const float* rp = resid + base;
            #pragma unroll
            for (int nf = 0; nf < 4; nf++) {
                int n = nt * 128 + wn + nf * 8 + 2 * (lane & 3);
                float2 rv = *(const float2*)&rp[n];
                float2 o;
                o.x = acc[mf][nf][hf * 2 + 0] + bv + rv.x;
                o.y = acc[mf][nf][hf * 2 + 1] + bv + rv.y;
                *(float2*)&dst[n] = o;
            }
        }
    }
}

// ============================================================
// host launch
// ============================================================
extern "C" void kernel_launch(void* const* d_in, const int* in_sizes, int n_in,
                              void* d_out, int out_size) {
    const float* x    = (const float*)d_in[0];
    const float* gnw  = (const float*)d_in[1];
    const float* gnb  = (const float*)d_in[2];
    const float* qkvW = (const float*)d_in[3];
    const float* ow   = (const float*)d_in[4];
    const float* ob   = (const float*)d_in[5];
    float* out = (float*)d_out;

    float* pBias3;
    __half *pXT, *pW3;
    cudaGetSymbolAddress((void**)&pBias3, d_bias3);
    cudaGetSymbolAddress((void**)&pXT, d_xT);
    cudaGetSymbolAddress((void**)&pW3, d_W3);

    cudaFuncSetAttribute(kv_sim, cudaFuncAttributeMaxDynamicSharedMemorySize, KV_SMEM);
    cudaFuncSetAttribute(gemm_out, cudaFuncAttributeMaxDynamicSharedMemorySize, GEMM_SMEM);

    tconv_stats<<<dim3(1024, 4, 4), dim3(32, 8)>>>(x, pXT);
    gn_stats2<<<16, 256>>>(gnw, gnb);
    build_wp<<<dim3(768, 4), 256>>>(qkvW);

    kv_sim<<<dim3(8, 128, 4), 256, KV_SMEM>>>();
    sim_reduce<<<32, 1024>>>();
    build_w2<<<dim3(256, 4), 256>>>(ow);
    build_w3<<<dim3(256, 4), 256>>>(ob);

    gemm_out<<<dim3(2, 256, 4), 256, GEMM_SMEM>>>(pW3, pXT, pBias3, x, out);
}

// round 13
// speedup vs baseline: 1.1572x; 1.1572x over previous
#include <cuda_runtime.h>
#include <cuda_fp16.h>
#include <cstdint>

// Problem constants
static constexpr int B_ = 4;
static constexpr int C_ = 256;
static constexpr int N_ = 32768;     // 32*32*32
static constexpr int H_ = 8;
static constexpr int NCH = 128;      // n-chunks of 256

// ---------------- device scratch (no allocations allowed) ----------------
__device__ __half d_xT[(long)B_ * N_ * C_];        // xT [b][n][c] fp16
__device__ __half d_Wp[B_ * 768 * C_];             // GN-folded qkv weight fp16
__device__ float d_biasp[B_ * 768];
__device__ __half d_W3[B_ * C_ * C_];              // W2 @ Wq' fp16
__device__ float d_bias3[B_ * C_];
__device__ float2 d_gpart[16 * 1024];              // GN partials (sum, sumsq)
__device__ float d_scale[B_ * C_];
__device__ float d_shift[B_ * C_];
__device__ float d_cm[(long)B_ * H_ * NCH * 32];   // per-chunk k row max
__device__ float d_cs[(long)B_ * H_ * NCH * 32];   // per-chunk sumexp
__device__ float d_simpart[(long)B_ * H_ * NCH * 1024];
__device__ float d_sp2[(long)B_ * H_ * 8 * 1024];  // second-level partials
__device__ float d_m[B_ * H_ * 32];                // row max
__device__ float d_s[B_ * H_ * 32];                // row sumexp
__device__ float d_sim[B_ * H_ * 1024];

// ---------------- PTX helpers ----------------
__device__ __forceinline__ uint32_t smem_u32(const void* p) {
    uint32_t a;
    asm("{ .reg .u64 t; cvta.to.shared.u64 t, %1; cvt.u32.u64 %0, t; }" : "=r"(a) : "l"(p));
    return a;
}
#define CP16(dst, src) asm volatile("cp.async.cg.shared.global [%0], [%1], 16;" :: "r"(dst), "l"(src))
#define CP_COMMIT()    asm volatile("cp.async.commit_group;")

__device__ __forceinline__ void ldm4(uint32_t* r, uint32_t addr) {
    asm volatile("ldmatrix.sync.aligned.m8n8.x4.shared.b16 {%0,%1,%2,%3}, [%4];"
        : "=r"(r[0]), "=r"(r[1]), "=r"(r[2]), "=r"(r[3]) : "r"(addr));
}
__device__ __forceinline__ void mma_f16(float* d, const uint32_t* a, const uint32_t* b) {
    asm volatile(
        "mma.sync.aligned.m16n8k16.row.col.f32.f16.f16.f32 "
        "{%0,%1,%2,%3}, {%4,%5,%6,%7}, {%8,%9}, {%0,%1,%2,%3};"
        : "+f"(d[0]), "+f"(d[1]), "+f"(d[2]), "+f"(d[3])
        : "r"(a[0]), "r"(a[1]), "r"(a[2]), "r"(a[3]), "r"(b[0]), "r"(b[1]));
}

// ============================================================
// Fused: x transpose->fp16 xT + GN partial stats.
// ============================================================
__global__ void tconv_stats(const float* __restrict__ x, __half* __restrict__ dst) {
    __shared__ float t[64][33];
    __shared__ float rs[256], rss[256];
    int n0 = blockIdx.x * 32, c0 = blockIdx.y * 64, b = blockIdx.z;
    const float* s = x + (long)b * C_ * N_;
    int tx = threadIdx.x, ty = threadIdx.y;
    int tid = ty * 32 + tx;
    float sum = 0.f, ss = 0.f;
    #pragma unroll
    for (int i = 0; i < 8; i++) {
        int cl = ty + i * 8;
        float v = s[(long)(c0 + cl) * N_ + n0 + tx];
        t[cl][tx] = v;
        sum += v; ss += v * v;
    }
    rs[tid] = sum; rss[tid] = ss;
    __syncthreads();
    __half* ph = dst + (long)b * N_ * C_;
    #pragma unroll
    for (int i = 0; i < 4; i++) {
        int nl = ty + i * 8;
        __half2 h = __floats2half2_rn(t[2 * tx][nl], t[2 * tx + 1][nl]);
        *(__half2*)&ph[(long)(n0 + nl) * C_ + c0 + 2 * tx] = h;
    }
    for (int st = 128; st > 0; st >>= 1) {
        if (tid < st) { rs[tid] += rs[tid + st]; rss[tid] += rss[tid + st]; }
        __syncthreads();
    }
    if (tid == 0)
        d_gpart[(b * 4 + blockIdx.y) * 1024 + blockIdx.x] = make_float2(rs[0], rss[0]);
}

__global__ void gn_stats2(const float* __restrict__ gnw, const float* __restrict__ gnb) {
    int bg = blockIdx.x, tid = threadIdx.x;
    __shared__ float rs[256], rss[256];
    float s = 0.f, ss = 0.f;
    for (int i = tid; i < 1024; i += 256) {
        float2 p = d_gpart[bg * 1024 + i];
        s += p.x; ss += p.y;
    }
    rs[tid] = s; rss[tid] = ss;
    __syncthreads();
    for (int st = 128; st > 0; st >>= 1) {
        if (tid < st) { rs[tid] += rs[tid + st]; rss[tid] += rss[tid + st]; }
        __syncthreads();
    }
    if (tid < 64) {
        float inv = 1.0f / (float)(64L * N_);
        float mean = rs[0] * inv;
        float var = rss[0] * inv - mean * mean;
        float rstd = rsqrtf(var + 1e-5f);
        int b = bg >> 2, g = bg & 3;
        int c = g * 64 + tid;
        float sc = rstd * gnw[c];
        d_scale[b * C_ + c] = sc;
        d_shift[b * C_ + c] = gnb[c] - mean * sc;
    }
}

__global__ void build_wp(const float* __restrict__ W) {
    int o = blockIdx.x, b = blockIdx.y, c = threadIdx.x;
    float w = W[o * C_ + c];
    d_Wp[((long)b * 768 + o) * C_ + c] = __float2half_rn(w * d_scale[b * C_ + c]);
    __shared__ float red[256];
    red[c] = w * d_shift[b * C_ + c];
    __syncthreads();
    for (int st = 128; st > 0; st >>= 1) {
        if (c < st) red[c] += red[c + st];
        __syncthreads();
    }
    if (c == 0) d_biasp[b * 768 + o] = red[0];
}

// ============================================================
// kv_sim: fused k/v GEMM + per-chunk softmax stats + sim partial.
// grid (h=8, nt=128, b=4), block 256 (8 warps).
// Barrier-free mainloop: A (64x256) resident in smem (528B rows),
// B warp-private 32-row slices, 3-buffer depth-2 cp.async ring.
// ============================================================
static constexpr int A_ROWB = 528;                 // 256 halves + 16B pad
static constexpr int A_BYTES = 64 * A_ROWB;        // 33792
static constexpr int B_ROWB = 80;                  // 32 halves + 16B pad
static constexpr int B_STG = 32 * B_ROWB;          // 2560 per warp per stage
static constexpr int B_WARP = 3 * B_STG;           // 7680
static constexpr int KV_SMEM = A_BYTES + 8 * B_WARP;   // 95232
static constexpr int XROW = 528;

__global__ void __launch_bounds__(256, 2) kv_sim() {
    extern __shared__ char smem[];
    uint32_t sb = smem_u32(smem);
    int tid = threadIdx.x, lane = tid & 31, wrp = tid >> 5;
    int h = blockIdx.x, nt = blockIdx.y, b = blockIdx.z;
    int wn = wrp * 32;

    const __half* Ak = d_Wp + ((long)b * 768 + 256 + h * 32) * 256;
    const __half* Av = d_Wp + ((long)b * 768 + 512 + h * 32) * 256;
    const __half* Bx = d_xT + ((long)b * N_ + nt * 256) * 256;

    uint32_t Abase = sb;
    uint32_t wb = sb + A_BYTES + wrp * B_WARP;

    // A cooperative load: 64 rows x 32 segs of 16B, 8 per thread
    #pragma unroll
    for (int it = 0; it < 8; it++) {
        int idx = tid + it * 256;
        int row = idx >> 5, seg = idx & 31;
        const __half* src = (row < 32 ? Ak + (long)row * 256
                                      : Av + (long)(row - 32) * 256) + seg * 8;
        CP16(Abase + row * A_ROWB + seg * 16, src);
    }
    CP_COMMIT();

    // warp-private B loader: 32 rows x 4 segs (128 CP16 / 32 lanes)
    auto loadB = [&](int kt) {
        uint32_t dst = wb + (kt % 3) * B_STG;
        int k0 = kt * 32;
        #pragma unroll
        for (int l = 0; l < 4; l++) {
            int idx = lane + l * 32;
            int row = idx >> 2, seg = idx & 3;
            CP16(dst + row * B_ROWB + seg * 16,
                 Bx + (long)(wn + row) * 256 + k0 + seg * 8);
        }
        CP_COMMIT();
    };
    loadB(0); loadB(1);

    float acc[4][4][4];
    #pragma unroll
    for (int i = 0; i < 4; i++)
        #pragma unroll
        for (int j = 0; j < 4; j++)
            #pragma unroll
            for (int e = 0; e < 4; e++) acc[i][j][e] = 0.f;

    int quad = lane >> 3, qr = lane & 7;
    int a_row = (quad & 1) * 8 + qr;
    int a_cb = (quad >> 1) * 16;
    int b_row = ((lane >> 4) & 1) * 8 + (lane & 7);
    int b_cb = ((lane >> 3) & 1) * 16;

    #pragma unroll 1
    for (int kt = 0; kt < 8; kt++) {
        if (kt < 7) { asm volatile("cp.async.wait_group 1;"); }
        else        { asm volatile("cp.async.wait_group 0;"); }
        if (kt == 0) __syncthreads();   // A visibility across warps
        else         __syncwarp();

        uint32_t bS = wb + (kt % 3) * B_STG;
        #pragma unroll
        for (int k16 = 0; k16 < 2; k16++) {
            uint32_t acol = kt * 64 + k16 * 32 + a_cb;
            uint32_t bcol = k16 * 32 + b_cb;
            uint32_t ah[4][4], bh[4][2];
            #pragma unroll
            for (int mf = 0; mf < 4; mf++)
                ldm4(ah[mf], Abase + (a_row + mf * 16) * A_ROWB + acol);
            #pragma unroll
            for (int nfp = 0; nfp < 2; nfp++) {
                uint32_t r4[4];
                ldm4(r4, bS + (b_row + nfp * 16) * B_ROWB + bcol);
                bh[nfp * 2 + 0][0] = r4[0]; bh[nfp * 2 + 0][1] = r4[1];
                bh[nfp * 2 + 1][0] = r4[2]; bh[nfp * 2 + 1][1] = r4[3];
            }
            #pragma unroll
            for (int mf = 0; mf < 4; mf++)
                #pragma unroll
                for (int nf = 0; nf < 4; nf++)
                    mma_f16(acc[mf][nf], ah[mf], bh[nf]);
        }
        if (kt + 2 < 8) loadB(kt + 2);   // after consuming kt: buffer (kt+2)%3 free
    }
    __syncthreads();   // phase 1 done everywhere; smem reused below

    // ---- overlay layout ----
    char* kx = smem;                       // 32 x 528
    char* vx = smem + 16896;               // 32 x 528
    float* red = (float*)(smem + 33792);   // 8 x 1024 floats
    float* sm_m = (float*)(smem + 66560);  // [32][8]
    float* sm_s = (float*)(smem + 67584);  // [32][8]
    float* gm   = (float*)(smem + 68608);  // [32]

    long bhc = ((long)(b * H_ + h) * NCH + nt);
    const float* bp = d_biasp + b * 768;

    // pass A: v -> vx fp16; k -> per-warp row max
    #pragma unroll
    for (int mf = 0; mf < 4; mf++) {
        #pragma unroll
        for (int hf = 0; hf < 2; hf++) {
            int r = mf * 16 + hf * 8 + (lane >> 2);
            if (mf < 2) {
                float bv = bp[256 + h * 32 + r];
                float mx = -1e30f;
                #pragma unroll
                for (int nf = 0; nf < 4; nf++) {
                    mx = fmaxf(mx, acc[mf][nf][hf * 2] + bv);
                    mx = fmaxf(mx, acc[mf][nf][hf * 2 + 1] + bv);
                }
                mx = fmaxf(mx, __shfl_xor_sync(0xffffffffu, mx, 1));
                mx = fmaxf(mx, __shfl_xor_sync(0xffffffffu, mx, 2));
                if ((lane & 3) == 0) sm_m[r * 8 + wrp] = mx;
            } else {
                int e = r - 32;
                float bv = bp[512 + h * 32 + e];
                #pragma unroll
                for (int nf = 0; nf < 4; nf++) {
                    int c = wn + nf * 8 + 2 * (lane & 3);
                    *(__half2*)(vx + e * XROW + c * 2) =
                        __floats2half2_rn(acc[mf][nf][hf * 2] + bv,
                                          acc[mf][nf][hf * 2 + 1] + bv);
                }
            }
        }
    }
    __syncthreads();
    if (tid < 32) {
        float mx = sm_m[tid * 8];
        #pragma unroll
        for (int ww = 1; ww < 8; ww++) mx = fmaxf(mx, sm_m[tid * 8 + ww]);
        gm[tid] = mx;
    }
    __syncthreads();

    // pass B: expk -> kx fp16 + per-warp sumexp
    #pragma unroll
    for (int mf = 0; mf < 2; mf++) {
        #pragma unroll
        for (int hf = 0; hf < 2; hf++) {
            int r = mf * 16 + hf * 8 + (lane >> 2);
            float bv = bp[256 + h * 32 + r];
            float m = gm[r];
            float ssum = 0.f;
            #pragma unroll
            for (int nf = 0; nf < 4; nf++) {
                int c = wn + nf * 8 + 2 * (lane & 3);
                float e0 = __expf(acc[mf][nf][hf * 2] + bv - m);
                float e1 = __expf(acc[mf][nf][hf * 2 + 1] + bv - m);
                ssum += e0 + e1;
                *(__half2*)(kx + r * XROW + c * 2) = __floats2half2_rn(e0, e1);
            }
            ssum += __shfl_xor_sync(0xffffffffu, ssum, 1);
            ssum += __shfl_xor_sync(0xffffffffu, ssum, 2);
            if ((lane & 3) == 0) sm_s[r * 8 + wrp] = ssum;
        }
    }
    __syncthreads();
    if (tid < 32) {
        float s = 0.f;
        #pragma unroll
        for (int ww = 0; ww < 8; ww++) s += sm_s[tid * 8 + ww];
        d_cm[bhc * 32 + tid] = gm[tid];
        d_cs[bhc * 32 + tid] = s;
    }

    // phase 2: simpart = expk(32x256) @ v(32x256)^T, warp = 64-wide K slice
    float acc2[2][4][4];
    #pragma unroll
    for (int i = 0; i < 2; i++)
        #pragma unroll
        for (int j = 0; j < 4; j++)
            #pragma unroll
            for (int e = 0; e < 4; e++) acc2[i][j][e] = 0.f;

    uint32_t kxu = smem_u32(kx), vxu = smem_u32(vx);
    int a2_row = (quad & 1) * 8 + qr;
    int b2_row = ((lane >> 4) & 1) * 8 + (lane & 7);
    uint32_t colb = wrp * 64;
    #pragma unroll
    for (int k16 = 0; k16 < 2; k16++) {
        uint32_t ac = colb + k16 * 32 + a_cb;
        uint32_t bc = colb + k16 * 32 + b_cb;
        uint32_t af[2][4], bf[4][2];
        #pragma unroll
        for (int mf = 0; mf < 2; mf++)
            ldm4(af[mf], kxu + (a2_row + mf * 16) * XROW + ac);
        #pragma unroll
        for (int nfp = 0; nfp < 2; nfp++) {
            uint32_t r4[4];
            ldm4(r4, vxu + (b2_row + nfp * 16) * XROW + bc);
            bf[nfp * 2 + 0][0] = r4[0]; bf[nfp * 2 + 0][1] = r4[1];
            bf[nfp * 2 + 1][0] = r4[2]; bf[nfp * 2 + 1][1] = r4[3];
        }
        #pragma unroll
        for (int mf = 0; mf < 2; mf++)
            #pragma unroll
            for (int nf = 0; nf < 4; nf++)
                mma_f16(acc2[mf][nf], af[mf], bf[nf]);
    }

    float* my = red + wrp * 1024;
    #pragma unroll
    for (int mf = 0; mf < 2; mf++) {
        int r = mf * 16 + (lane >> 2);
        #pragma unroll
        for (int nf = 0; nf < 4; nf++) {
            int c = nf * 8 + 2 * (lane & 3);
            my[r * 32 + c]           = acc2[mf][nf][0];
            my[r * 32 + c + 1]       = acc2[mf][nf][1];
            my[(r + 8) * 32 + c]     = acc2[mf][nf][2];
            my[(r + 8) * 32 + c + 1] = acc2[mf][nf][3];
        }
    }
    __syncthreads();
    float* outp = d_simpart + bhc * 1024;
    for (int i = tid; i < 1024; i += 256) {
        float s = 0.f;
        #pragma unroll
        for (int ww = 0; ww < 8; ww++) s += red[ww * 1024 + i];
        outp[i] = s;
    }
}

// ============================================================
// krow_final: global (M, S) per k-row from chunk stats.
// grid 32 (bh), block 1024 (32 parts x 32 d).
// ============================================================
__global__ void krow_final() {
    __shared__ float mx[1024], sx[1024];
    int bh = blockIdx.x, tid = threadIdx.x;
    int d = tid & 31, part = tid >> 5;
    const float* cmp = d_cm + (long)bh * NCH * 32;
    const float* csp = d_cs + (long)bh * NCH * 32;
    float M = -1e30f;
    #pragma unroll
    for (int c = 0; c < 4; c++)
        M = fmaxf(M, cmp[(part * 4 + c) * 32 + d]);
    mx[tid] = M;
    __syncthreads();
    for (int st = 512; st >= 32; st >>= 1) {
        if (tid < st) mx[tid] = fmaxf(mx[tid], mx[tid + st]);
        __syncthreads();
    }
    float Mg = mx[d];
    __syncthreads();
    float S = 0.f;
    #pragma unroll
    for (int c = 0; c < 4; c++) {
        int ch = part * 4 + c;
        S += __expf(cmp[ch * 32 + d] - Mg) * csp[ch * 32 + d];
    }
    sx[tid] = S;
    __syncthreads();
    for (int st = 512; st >= 32; st >>= 1) {
        if (tid < st) sx[tid] += sx[tid + st];
        __syncthreads();
    }
    if (tid < 32) { d_m[bh * 32 + tid] = mx[tid]; d_s[bh * 32 + tid] = sx[tid]; }
}

// ============================================================
// sim_part2: 16-chunk weighted partials. grid (32 bh, 8 p), block 1024.
// ============================================================
__global__ void sim_part2() {
    int bh = blockIdx.x, p = blockIdx.y, i = threadIdx.x;
    int d = i >> 5;
    float M = d_m[bh * 32 + d];
    const float* cmp = d_cm + (long)bh * NCH * 32;
    const float* base = d_simpart + (long)bh * NCH * 1024;
    float acc = 0.f;
    #pragma unroll 4
    for (int c = 0; c < 16; c++) {
        int ch = p * 16 + c;
        float w = __expf(cmp[ch * 32 + d] - M);
        acc += w * base[(long)ch * 1024 + i];
    }
    d_sp2[((long)bh * 8 + p) * 1024 + i] = acc;
}

// sim_final: merge 8 partials (division deferred to build_w23)
__global__ void sim_final() {
    int bh = blockIdx.x, i = threadIdx.x;
    float s = 0.f;
    #pragma unroll
    for (int p = 0; p < 8; p++)
        s += d_sp2[((long)bh * 8 + p) * 1024 + i];
    d_sim[bh * 1024 + i] = s;
}

// ============================================================
// build_w23: W2 row (in smem) -> W3 row + bias3. grid (256, 4), 256 thr.
// ============================================================
__global__ void build_w23(const float* __restrict__ OW, const float* __restrict__ ob) {
    int o = blockIdx.x, b = blockIdx.y, cp = threadIdx.x;
    int h = cp >> 5, d = cp & 31;
    int bh = b * 8 + h;
    __shared__ float w2row[256];
    __shared__ float red[256];
    const float* simp = d_sim + (long)(bh * 32 + d) * 32;
    const float* owp = OW + o * C_ + h * 32;
    float s = 0.f;
    #pragma unroll
    for (int e = 0; e < 32; e++) s += owp[e] * simp[e];
    s *= 1.0f / d_s[bh * 32 + d];
    w2row[cp] = s;
    red[cp] = s * d_biasp[b * 768 + cp];
    __syncthreads();
    float acc = 0.f;
    const __half* wq = d_Wp + (long)b * 768 * C_;
    #pragma unroll 8
    for (int e = 0; e < 256; e++)
        acc += w2row[e] * __half2float(wq[(long)e * C_ + cp]);
    d_W3[((long)b * C_ + o) * C_ + cp] = __float2half_rn(acc);
    for (int st = 128; st > 0; st >>= 1) {
        if (cp < st) red[cp] += red[cp + st];
        __syncthreads();
    }
    if (cp == 0) d_bias3[b * C_ + o] = ob[o] + red[0];
}

// ============================================================
// out GEMM: out = W3 @ xT^T + bias3 + x. BK=64, 3-stage.
// ============================================================
static constexpr int SKROW = 72;
static constexpr int TILE_BYTES = 128 * SKROW * 2;   // 18432
static constexpr int STAGE_BYTES = 2 * TILE_BYTES;   // 36864
static constexpr int GEMM_SMEM = 3 * STAGE_BYTES;    // 110592

__device__ __forceinline__ void load_stage(
    uint32_t sbase, const __half* A, const __half* Bm, int kt, int tid)
{
    int k0 = kt * 64;
    #pragma unroll
    for (int it = 0; it < 4; it++) {
        int i = tid + it * 256;
        int row = i >> 3, seg = i & 7;
        uint32_t doff = row * (SKROW * 2) + seg * 16;
        long goff = (long)row * 256 + k0 + seg * 8;
        CP16(sbase + doff,              A + goff);
        CP16(sbase + TILE_BYTES + doff, Bm + goff);
    }
}

__global__ void __launch_bounds__(256, 2) gemm_out(
    const __half* __restrict__ Amat, const __half* __restrict__ Bmat,
    const float* __restrict__ bias, const float* __restrict__ resid,
    float* __restrict__ outO)
{
    extern __shared__ char smem[];
    uint32_t sb = smem_u32(smem);
    int tid = threadIdx.x;
    int warp = tid >> 5, lane = tid & 31;
    int wm = (warp >> 2) * 64;
    int wn = (warp & 3) * 32;
    int mt = blockIdx.x, nt = blockIdx.y, b = blockIdx.z;

    const __half* A = Amat + (long)b * 256 * 256 + (long)mt * 128 * 256;
    const __half* Bm = Bmat + (long)b * N_ * 256 + (long)nt * 128 * 256;

    float acc[4][4][4];
    #pragma unroll
    for (int i = 0; i < 4; i++)
        #pragma unroll
        for (int j = 0; j < 4; j++)
            #pragma unroll
            for (int e = 0; e < 4; e++) acc[i][j][e] = 0.f;

    load_stage(sb + 0 * STAGE_BYTES, A, Bm, 0, tid); CP_COMMIT();
    load_stage(sb + 1 * STAGE_BYTES, A, Bm, 1, tid); CP_COMMIT();

    int quad = lane >> 3, qr = lane & 7;
    int a_row = wm + (quad & 1) * 8 + qr;
    int a_colb = (quad >> 1) * 16;
    int b_row = wn + ((lane >> 4) & 1) * 8 + (lane & 7);
    int b_colb = ((lane >> 3) & 1) * 16;

    #pragma unroll 1
    for (int kt = 0; kt < 4; kt++) {
        if (kt + 1 < 4) { asm volatile("cp.async.wait_group 1;"); }
        else            { asm volatile("cp.async.wait_group 0;"); }
        __syncthreads();
        if (kt + 2 < 4) {
            load_stage(sb + ((kt + 2) % 3) * STAGE_BYTES, A, Bm, kt + 2, tid);
            CP_COMMIT();
        }
        uint32_t base = sb + (kt % 3) * STAGE_BYTES;
        uint32_t aS = base, bS = base + TILE_BYTES;
        #pragma unroll
        for (int k16 = 0; k16 < 4; k16++) {
            uint32_t acol = a_colb + k16 * 32;
            uint32_t bcol = b_colb + k16 * 32;
            uint32_t ah[4][4], bh[4][2];
            #pragma unroll
            for (int mf = 0; mf < 4; mf++)
                ldm4(ah[mf], aS + (a_row + mf * 16) * (SKROW * 2) + acol);
            #pragma unroll
            for (int nfp = 0; nfp < 2; nfp++) {
                uint32_t r4[4];
                ldm4(r4, bS + (b_row + nfp * 16) * (SKROW * 2) + bcol);
                bh[nfp * 2 + 0][0] = r4[0]; bh[nfp * 2 + 0][1] = r4[1];
                bh[nfp * 2 + 1][0] = r4[2]; bh[nfp * 2 + 1][1] = r4[3];
            }
            #pragma unroll
            for (int mf = 0; mf < 4; mf++)
                #pragma unroll
                for (int nf = 0; nf < 4; nf++)
                    mma_f16(acc[mf][nf], ah[mf], bh[nf]);
        }
    }

    #pragma unroll
    for (int mf = 0; mf < 4; mf++) {
        #pragma unroll
        for (int hf = 0; hf < 2; hf++) {
            int mrow = mt * 128 + wm + mf * 16 + hf * 8 + (lane >> 2);
            float bv = bias[b * C_ + mrow];
            long base = ((long)b * C_ + mrow) * N_;
            float* dst = outO + base;
            const float* rp = resid + base;
            #pragma unroll
            for (int nf = 0; nf < 4; nf++) {
                int n = nt * 128 + wn + nf * 8 + 2 * (lane & 3);
                float2 rv = *(const float2*)&rp[n];
                float2 o;
                o.x = acc[mf][nf][hf * 2 + 0] + bv + rv.x;
                o.y = acc[mf][nf][hf * 2 + 1] + bv + rv.y;
                *(float2*)&dst[n] = o;
            }
        }
    }
}

// ============================================================
// host launch
// ============================================================
extern "C" void kernel_launch(void* const* d_in, const int* in_sizes, int n_in,
                              void* d_out, int out_size) {
    const float* x    = (const float*)d_in[0];
    const float* gnw  = (const float*)d_in[1];
    const float* gnb  = (const float*)d_in[2];
    const float* qkvW = (const float*)d_in[3];
    const float* ow   = (const float*)d_in[4];
    const float* ob   = (const float*)d_in[5];
    float* out = (float*)d_out;

    float* pBias3;
    __half *pXT, *pW3;
    cudaGetSymbolAddress((void**)&pBias3, d_bias3);
    cudaGetSymbolAddress((void**)&pXT, d_xT);
    cudaGetSymbolAddress((void**)&pW3, d_W3);

    cudaFuncSetAttribute(kv_sim, cudaFuncAttributeMaxDynamicSharedMemorySize, KV_SMEM);
    cudaFuncSetAttribute(gemm_out, cudaFuncAttributeMaxDynamicSharedMemorySize, GEMM_SMEM);

    tconv_stats<<<dim3(1024, 4, 4), dim3(32, 8)>>>(x, pXT);
    gn_stats2<<<16, 256>>>(gnw, gnb);
    build_wp<<<dim3(768, 4), 256>>>(qkvW);

    kv_sim<<<dim3(8, 128, 4), 256, KV_SMEM>>>();
    krow_final<<<32, 1024>>>();
    sim_part2<<<dim3(32, 8), 1024>>>();
    sim_final<<<32, 1024>>>();
    build_w23<<<dim3(256, 4), 256>>>(ow, ob);

    gemm_out<<<dim3(2, 256, 4), 256, GEMM_SMEM>>>(pW3, pXT, pBias3, x, out);
}

// round 14
// speedup vs baseline: 1.1765x; 1.0167x over previous
#include <cuda_runtime.h>
#include <cuda_fp16.h>
#include <cstdint>

// Problem constants
static constexpr int B_ = 4;
static constexpr int C_ = 256;
static constexpr int N_ = 32768;     // 32*32*32
static constexpr int H_ = 8;
static constexpr int NCH = 128;      // n-chunks of 256

// ---------------- device scratch (no allocations allowed) ----------------
__device__ __half d_xT[(long)B_ * N_ * C_];        // xT [b][n][c] fp16
__device__ __half d_Wp[B_ * 768 * C_];             // GN-folded qkv weight fp16
__device__ float d_biasp[B_ * 768];
__device__ __half d_W3[B_ * C_ * C_];              // W2 @ Wq' fp16
__device__ float d_bias3[B_ * C_];
__device__ float2 d_gpart[16 * 1024];              // GN partials (sum, sumsq)
__device__ float d_scale[B_ * C_];
__device__ float d_shift[B_ * C_];
__device__ float d_cm[(long)B_ * H_ * NCH * 32];   // per-chunk k row max
__device__ float d_cs[(long)B_ * H_ * NCH * 32];   // per-chunk sumexp
__device__ float d_simpart[(long)B_ * H_ * NCH * 1024];
__device__ float d_sp2[(long)B_ * H_ * 8 * 1024];  // second-level partials
__device__ float d_m[B_ * H_ * 32];                // row max
__device__ float d_s[B_ * H_ * 32];                // row sumexp
__device__ float d_sim[B_ * H_ * 1024];

// ---------------- PTX helpers ----------------
__device__ __forceinline__ uint32_t smem_u32(const void* p) {
    uint32_t a;
    asm("{ .reg .u64 t; cvta.to.shared.u64 t, %1; cvt.u32.u64 %0, t; }" : "=r"(a) : "l"(p));
    return a;
}
#define CP16(dst, src) asm volatile("cp.async.cg.shared.global [%0], [%1], 16;" :: "r"(dst), "l"(src))
#define CP_COMMIT()    asm volatile("cp.async.commit_group;")

__device__ __forceinline__ void ldm4(uint32_t* r, uint32_t addr) {
    asm volatile("ldmatrix.sync.aligned.m8n8.x4.shared.b16 {%0,%1,%2,%3}, [%4];"
        : "=r"(r[0]), "=r"(r[1]), "=r"(r[2]), "=r"(r[3]) : "r"(addr));
}
__device__ __forceinline__ void mma_f16(float* d, const uint32_t* a, const uint32_t* b) {
    asm volatile(
        "mma.sync.aligned.m16n8k16.row.col.f32.f16.f16.f32 "
        "{%0,%1,%2,%3}, {%4,%5,%6,%7}, {%8,%9}, {%0,%1,%2,%3};"
        : "+f"(d[0]), "+f"(d[1]), "+f"(d[2]), "+f"(d[3])
        : "r"(a[0]), "r"(a[1]), "r"(a[2]), "r"(a[3]), "r"(b[0]), "r"(b[1]));
}

// ============================================================
// Fused: x transpose->fp16 xT + GN partial stats.
// ============================================================
__global__ void tconv_stats(const float* __restrict__ x, __half* __restrict__ dst) {
    __shared__ float t[64][33];
    __shared__ float rs[256], rss[256];
    int n0 = blockIdx.x * 32, c0 = blockIdx.y * 64, b = blockIdx.z;
    const float* s = x + (long)b * C_ * N_;
    int tx = threadIdx.x, ty = threadIdx.y;
    int tid = ty * 32 + tx;
    float sum = 0.f, ss = 0.f;
    #pragma unroll
    for (int i = 0; i < 8; i++) {
        int cl = ty + i * 8;
        float v = s[(long)(c0 + cl) * N_ + n0 + tx];
        t[cl][tx] = v;
        sum += v; ss += v * v;
    }
    rs[tid] = sum; rss[tid] = ss;
    __syncthreads();
    __half* ph = dst + (long)b * N_ * C_;
    #pragma unroll
    for (int i = 0; i < 4; i++) {
        int nl = ty + i * 8;
        __half2 h = __floats2half2_rn(t[2 * tx][nl], t[2 * tx + 1][nl]);
        *(__half2*)&ph[(long)(n0 + nl) * C_ + c0 + 2 * tx] = h;
    }
    for (int st = 128; st > 0; st >>= 1) {
        if (tid < st) { rs[tid] += rs[tid + st]; rss[tid] += rss[tid + st]; }
        __syncthreads();
    }
    if (tid == 0)
        d_gpart[(b * 4 + blockIdx.y) * 1024 + blockIdx.x] = make_float2(rs[0], rss[0]);
}

__global__ void gn_stats2(const float* __restrict__ gnw, const float* __restrict__ gnb) {
    int bg = blockIdx.x, tid = threadIdx.x;
    __shared__ float rs[256], rss[256];
    float s = 0.f, ss = 0.f;
    for (int i = tid; i < 1024; i += 256) {
        float2 p = d_gpart[bg * 1024 + i];
        s += p.x; ss += p.y;
    }
    rs[tid] = s; rss[tid] = ss;
    __syncthreads();
    for (int st = 128; st > 0; st >>= 1) {
        if (tid < st) { rs[tid] += rs[tid + st]; rss[tid] += rss[tid + st]; }
        __syncthreads();
    }
    if (tid < 64) {
        float inv = 1.0f / (float)(64L * N_);
        float mean = rs[0] * inv;
        float var = rss[0] * inv - mean * mean;
        float rstd = rsqrtf(var + 1e-5f);
        int b = bg >> 2, g = bg & 3;
        int c = g * 64 + tid;
        float sc = rstd * gnw[c];
        d_scale[b * C_ + c] = sc;
        d_shift[b * C_ + c] = gnb[c] - mean * sc;
    }
}

__global__ void build_wp(const float* __restrict__ W) {
    int o = blockIdx.x, b = blockIdx.y, c = threadIdx.x;
    float w = W[o * C_ + c];
    d_Wp[((long)b * 768 + o) * C_ + c] = __float2half_rn(w * d_scale[b * C_ + c]);
    __shared__ float red[256];
    red[c] = w * d_shift[b * C_ + c];
    __syncthreads();
    for (int st = 128; st > 0; st >>= 1) {
        if (c < st) red[c] += red[c + st];
        __syncthreads();
    }
    if (c == 0) d_biasp[b * 768 + o] = red[0];
}

// ============================================================
// Shared tile geometry for barrier-free M=64 x N=256 GEMMs.
// ============================================================
static constexpr int A_ROWB = 528;                 // 256 halves + 16B pad
static constexpr int A_BYTES = 64 * A_ROWB;        // 33792
static constexpr int B_ROWB = 80;                  // 32 halves + 16B pad
static constexpr int B_STG = 32 * B_ROWB;          // 2560 per warp per stage
static constexpr int B_WARP = 3 * B_STG;           // 7680
static constexpr int KV_SMEM = A_BYTES + 8 * B_WARP;   // 95232
static constexpr int XROW = 528;

// ============================================================
// kv_sim: fused k/v GEMM + per-chunk softmax stats + sim partial.
// grid (h=8, nt=128, b=4), block 256 (8 warps). Barrier-free mainloop.
// ============================================================
__global__ void __launch_bounds__(256, 2) kv_sim() {
    extern __shared__ char smem[];
    uint32_t sb = smem_u32(smem);
    int tid = threadIdx.x, lane = tid & 31, wrp = tid >> 5;
    int h = blockIdx.x, nt = blockIdx.y, b = blockIdx.z;
    int wn = wrp * 32;

    const __half* Ak = d_Wp + ((long)b * 768 + 256 + h * 32) * 256;
    const __half* Av = d_Wp + ((long)b * 768 + 512 + h * 32) * 256;
    const __half* Bx = d_xT + ((long)b * N_ + nt * 256) * 256;

    uint32_t Abase = sb;
    uint32_t wb = sb + A_BYTES + wrp * B_WARP;

    #pragma unroll
    for (int it = 0; it < 8; it++) {
        int idx = tid + it * 256;
        int row = idx >> 5, seg = idx & 31;
        const __half* src = (row < 32 ? Ak + (long)row * 256
                                      : Av + (long)(row - 32) * 256) + seg * 8;
        CP16(Abase + row * A_ROWB + seg * 16, src);
    }
    CP_COMMIT();

    auto loadB = [&](int kt) {
        uint32_t dst = wb + (kt % 3) * B_STG;
        int k0 = kt * 32;
        #pragma unroll
        for (int l = 0; l < 4; l++) {
            int idx = lane + l * 32;
            int row = idx >> 2, seg = idx & 3;
            CP16(dst + row * B_ROWB + seg * 16,
                 Bx + (long)(wn + row) * 256 + k0 + seg * 8);
        }
        CP_COMMIT();
    };
    loadB(0); loadB(1);

    float acc[4][4][4];
    #pragma unroll
    for (int i = 0; i < 4; i++)
        #pragma unroll
        for (int j = 0; j < 4; j++)
            #pragma unroll
            for (int e = 0; e < 4; e++) acc[i][j][e] = 0.f;

    int quad = lane >> 3, qr = lane & 7;
    int a_row = (quad & 1) * 8 + qr;
    int a_cb = (quad >> 1) * 16;
    int b_row = ((lane >> 4) & 1) * 8 + (lane & 7);
    int b_cb = ((lane >> 3) & 1) * 16;

    #pragma unroll 1
    for (int kt = 0; kt < 8; kt++) {
        if (kt < 7) { asm volatile("cp.async.wait_group 1;"); }
        else        { asm volatile("cp.async.wait_group 0;"); }
        if (kt == 0) __syncthreads();
        else         __syncwarp();
        if (kt + 2 < 8) loadB(kt + 2);   // buffer (kt+2)%3 consumed in iter kt-1

        uint32_t bS = wb + (kt % 3) * B_STG;
        #pragma unroll
        for (int k16 = 0; k16 < 2; k16++) {
            uint32_t acol = kt * 64 + k16 * 32 + a_cb;
            uint32_t bcol = k16 * 32 + b_cb;
            uint32_t ah[4][4], bh[4][2];
            #pragma unroll
            for (int mf = 0; mf < 4; mf++)
                ldm4(ah[mf], Abase + (a_row + mf * 16) * A_ROWB + acol);
            #pragma unroll
            for (int nfp = 0; nfp < 2; nfp++) {
                uint32_t r4[4];
                ldm4(r4, bS + (b_row + nfp * 16) * B_ROWB + bcol);
                bh[nfp * 2 + 0][0] = r4[0]; bh[nfp * 2 + 0][1] = r4[1];
                bh[nfp * 2 + 1][0] = r4[2]; bh[nfp * 2 + 1][1] = r4[3];
            }
            #pragma unroll
            for (int mf = 0; mf < 4; mf++)
                #pragma unroll
                for (int nf = 0; nf < 4; nf++)
                    mma_f16(acc[mf][nf], ah[mf], bh[nf]);
        }
    }
    __syncthreads();

    // ---- overlay layout ----
    char* kx = smem;                       // 32 x 528
    char* vx = smem + 16896;               // 32 x 528
    float* red = (float*)(smem + 33792);   // 8 x 1024 floats
    float* sm_m = (float*)(smem + 66560);  // [32][8]
    float* sm_s = (float*)(smem + 67584);  // [32][8]
    float* gm   = (float*)(smem + 68608);  // [32]

    long bhc = ((long)(b * H_ + h) * NCH + nt);
    const float* bp = d_biasp + b * 768;

    #pragma unroll
    for (int mf = 0; mf < 4; mf++) {
        #pragma unroll
        for (int hf = 0; hf < 2; hf++) {
            int r = mf * 16 + hf * 8 + (lane >> 2);
            if (mf < 2) {
                float bv = bp[256 + h * 32 + r];
                float mx = -1e30f;
                #pragma unroll
                for (int nf = 0; nf < 4; nf++) {
                    mx = fmaxf(mx, acc[mf][nf][hf * 2] + bv);
                    mx = fmaxf(mx, acc[mf][nf][hf * 2 + 1] + bv);
                }
                mx = fmaxf(mx, __shfl_xor_sync(0xffffffffu, mx, 1));
                mx = fmaxf(mx, __shfl_xor_sync(0xffffffffu, mx, 2));
                if ((lane & 3) == 0) sm_m[r * 8 + wrp] = mx;
            } else {
                int e = r - 32;
                float bv = bp[512 + h * 32 + e];
                #pragma unroll
                for (int nf = 0; nf < 4; nf++) {
                    int c = wn + nf * 8 + 2 * (lane & 3);
                    *(__half2*)(vx + e * XROW + c * 2) =
                        __floats2half2_rn(acc[mf][nf][hf * 2] + bv,
                                          acc[mf][nf][hf * 2 + 1] + bv);
                }
            }
        }
    }
    __syncthreads();
    if (tid < 32) {
        float mx = sm_m[tid * 8];
        #pragma unroll
        for (int ww = 1; ww < 8; ww++) mx = fmaxf(mx, sm_m[tid * 8 + ww]);
        gm[tid] = mx;
    }
    __syncthreads();

    #pragma unroll
    for (int mf = 0; mf < 2; mf++) {
        #pragma unroll
        for (int hf = 0; hf < 2; hf++) {
            int r = mf * 16 + hf * 8 + (lane >> 2);
            float bv = bp[256 + h * 32 + r];
            float m = gm[r];
            float ssum = 0.f;
            #pragma unroll
            for (int nf = 0; nf < 4; nf++) {
                int c = wn + nf * 8 + 2 * (lane & 3);
                float e0 = __expf(acc[mf][nf][hf * 2] + bv - m);
                float e1 = __expf(acc[mf][nf][hf * 2 + 1] + bv - m);
                ssum += e0 + e1;
                *(__half2*)(kx + r * XROW + c * 2) = __floats2half2_rn(e0, e1);
            }
            ssum += __shfl_xor_sync(0xffffffffu, ssum, 1);
            ssum += __shfl_xor_sync(0xffffffffu, ssum, 2);
            if ((lane & 3) == 0) sm_s[r * 8 + wrp] = ssum;
        }
    }
    __syncthreads();
    if (tid < 32) {
        float s = 0.f;
        #pragma unroll
        for (int ww = 0; ww < 8; ww++) s += sm_s[tid * 8 + ww];
        d_cm[bhc * 32 + tid] = gm[tid];
        d_cs[bhc * 32 + tid] = s;
    }

    float acc2[2][4][4];
    #pragma unroll
    for (int i = 0; i < 2; i++)
        #pragma unroll
        for (int j = 0; j < 4; j++)
            #pragma unroll
            for (int e = 0; e < 4; e++) acc2[i][j][e] = 0.f;

    uint32_t kxu = smem_u32(kx), vxu = smem_u32(vx);
    int a2_row = (quad & 1) * 8 + qr;
    int b2_row = ((lane >> 4) & 1) * 8 + (lane & 7);
    uint32_t colb = wrp * 64;
    #pragma unroll
    for (int k16 = 0; k16 < 2; k16++) {
        uint32_t ac = colb + k16 * 32 + a_cb;
        uint32_t bc = colb + k16 * 32 + b_cb;
        uint32_t af[2][4], bf[4][2];
        #pragma unroll
        for (int mf = 0; mf < 2; mf++)
            ldm4(af[mf], kxu + (a2_row + mf * 16) * XROW + ac);
        #pragma unroll
        for (int nfp = 0; nfp < 2; nfp++) {
            uint32_t r4[4];
            ldm4(r4, vxu + (b2_row + nfp * 16) * XROW + bc);
            bf[nfp * 2 + 0][0] = r4[0]; bf[nfp * 2 + 0][1] = r4[1];
            bf[nfp * 2 + 1][0] = r4[2]; bf[nfp * 2 + 1][1] = r4[3];
        }
        #pragma unroll
        for (int mf = 0; mf < 2; mf++)
            #pragma unroll
            for (int nf = 0; nf < 4; nf++)
                mma_f16(acc2[mf][nf], af[mf], bf[nf]);
    }

    float* my = red + wrp * 1024;
    #pragma unroll
    for (int mf = 0; mf < 2; mf++) {
        int r = mf * 16 + (lane >> 2);
        #pragma unroll
        for (int nf = 0; nf < 4; nf++) {
            int c = nf * 8 + 2 * (lane & 3);
            my[r * 32 + c]           = acc2[mf][nf][0];
            my[r * 32 + c + 1]       = acc2[mf][nf][1];
            my[(r + 8) * 32 + c]     = acc2[mf][nf][2];
            my[(r + 8) * 32 + c + 1] = acc2[mf][nf][3];
        }
    }
    __syncthreads();
    float* outp = d_simpart + bhc * 1024;
    for (int i = tid; i < 1024; i += 256) {
        float s = 0.f;
        #pragma unroll
        for (int ww = 0; ww < 8; ww++) s += red[ww * 1024 + i];
        outp[i] = s;
    }
}

// ============================================================
// krow_final: global (M, S) per k-row from chunk stats.
// ============================================================
__global__ void krow_final() {
    __shared__ float mx[1024], sx[1024];
    int bh = blockIdx.x, tid = threadIdx.x;
    int d = tid & 31, part = tid >> 5;
    const float* cmp = d_cm + (long)bh * NCH * 32;
    const float* csp = d_cs + (long)bh * NCH * 32;
    float M = -1e30f;
    #pragma unroll
    for (int c = 0; c < 4; c++)
        M = fmaxf(M, cmp[(part * 4 + c) * 32 + d]);
    mx[tid] = M;
    __syncthreads();
    for (int st = 512; st >= 32; st >>= 1) {
        if (tid < st) mx[tid] = fmaxf(mx[tid], mx[tid + st]);
        __syncthreads();
    }
    float Mg = mx[d];
    __syncthreads();
    float S = 0.f;
    #pragma unroll
    for (int c = 0; c < 4; c++) {
        int ch = part * 4 + c;
        S += __expf(cmp[ch * 32 + d] - Mg) * csp[ch * 32 + d];
    }
    sx[tid] = S;
    __syncthreads();
    for (int st = 512; st >= 32; st >>= 1) {
        if (tid < st) sx[tid] += sx[tid + st];
        __syncthreads();
    }
    if (tid < 32) { d_m[bh * 32 + tid] = mx[tid]; d_s[bh * 32 + tid] = sx[tid]; }
}

// ============================================================
// sim_part2: 16-chunk weighted partials. grid (32 bh, 8 p), block 1024.
// ============================================================
__global__ void sim_part2() {
    int bh = blockIdx.x, p = blockIdx.y, i = threadIdx.x;
    int d = i >> 5;
    float M = d_m[bh * 32 + d];
    const float* cmp = d_cm + (long)bh * NCH * 32;
    const float* base = d_simpart + (long)bh * NCH * 1024;
    float acc = 0.f;
    #pragma unroll 4
    for (int c = 0; c < 16; c++) {
        int ch = p * 16 + c;
        float w = __expf(cmp[ch * 32 + d] - M);
        acc += w * base[(long)ch * 1024 + i];
    }
    d_sp2[((long)bh * 8 + p) * 1024 + i] = acc;
}

__global__ void sim_final() {
    int bh = blockIdx.x, i = threadIdx.x;
    float s = 0.f;
    #pragma unroll
    for (int p = 0; p < 8; p++)
        s += d_sp2[((long)bh * 8 + p) * 1024 + i];
    d_sim[bh * 1024 + i] = s;
}

// ============================================================
// build_w23: W2 row (in smem) -> W3 row + bias3. grid (256, 4), 256 thr.
// ============================================================
__global__ void build_w23(const float* __restrict__ OW, const float* __restrict__ ob) {
    int o = blockIdx.x, b = blockIdx.y, cp = threadIdx.x;
    int h = cp >> 5, d = cp & 31;
    int bh = b * 8 + h;
    __shared__ float w2row[256];
    __shared__ float red[256];
    const float* simp = d_sim + (long)(bh * 32 + d) * 32;
    const float* owp = OW + o * C_ + h * 32;
    float s = 0.f;
    #pragma unroll
    for (int e = 0; e < 32; e++) s += owp[e] * simp[e];
    s *= 1.0f / d_s[bh * 32 + d];
    w2row[cp] = s;
    red[cp] = s * d_biasp[b * 768 + cp];
    __syncthreads();
    float acc = 0.f;
    const __half* wq = d_Wp + (long)b * 768 * C_;
    #pragma unroll 8
    for (int e = 0; e < 256; e++)
        acc += w2row[e] * __half2float(wq[(long)e * C_ + cp]);
    d_W3[((long)b * C_ + o) * C_ + cp] = __float2half_rn(acc);
    for (int st = 128; st > 0; st >>= 1) {
        if (cp < st) red[cp] += red[cp + st];
        __syncthreads();
    }
    if (cp == 0) d_bias3[b * C_ + o] = ob[o] + red[0];
}

// ============================================================
// gemm_out (barrier-free): out = W3 @ xT^T + bias3 + x.
// grid (mt=4, nt=128, b=4), block 256. M=64, N=256, same ring as kv_sim.
// ============================================================
__global__ void __launch_bounds__(256, 2) gemm_out(
    const __half* __restrict__ W3, const __half* __restrict__ XT,
    const float* __restrict__ bias, const float* __restrict__ resid,
    float* __restrict__ outO)
{
    extern __shared__ char smem[];
    uint32_t sb = smem_u32(smem);
    int tid = threadIdx.x, lane = tid & 31, wrp = tid >> 5;
    int mt = blockIdx.x, nt = blockIdx.y, b = blockIdx.z;
    int wn = wrp * 32;

    const __half* A = W3 + (long)b * C_ * C_ + (long)mt * 64 * 256;
    const __half* Bx = XT + ((long)b * N_ + nt * 256) * 256;

    uint32_t Abase = sb;
    uint32_t wb = sb + A_BYTES + wrp * B_WARP;

    #pragma unroll
    for (int it = 0; it < 8; it++) {
        int idx = tid + it * 256;
        int row = idx >> 5, seg = idx & 31;
        CP16(Abase + row * A_ROWB + seg * 16, A + (long)row * 256 + seg * 8);
    }
    CP_COMMIT();

    auto loadB = [&](int kt) {
        uint32_t dst = wb + (kt % 3) * B_STG;
        int k0 = kt * 32;
        #pragma unroll
        for (int l = 0; l < 4; l++) {
            int idx = lane + l * 32;
            int row = idx >> 2, seg = idx & 3;
            CP16(dst + row * B_ROWB + seg * 16,
                 Bx + (long)(wn + row) * 256 + k0 + seg * 8);
        }
        CP_COMMIT();
    };
    loadB(0); loadB(1);

    float acc[4][4][4];
    #pragma unroll
    for (int i = 0; i < 4; i++)
        #pragma unroll
        for (int j = 0; j < 4; j++)
            #pragma unroll
            for (int e = 0; e < 4; e++) acc[i][j][e] = 0.f;

    int quad = lane >> 3, qr = lane & 7;
    int a_row = (quad & 1) * 8 + qr;
    int a_cb = (quad >> 1) * 16;
    int b_row = ((lane >> 4) & 1) * 8 + (lane & 7);
    int b_cb = ((lane >> 3) & 1) * 16;

    #pragma unroll 1
    for (int kt = 0; kt < 8; kt++) {
        if (kt < 7) { asm volatile("cp.async.wait_group 1;"); }
        else        { asm volatile("cp.async.wait_group 0;"); }
        if (kt == 0) __syncthreads();
        else         __syncwarp();
        if (kt + 2 < 8) loadB(kt + 2);

        uint32_t bS = wb + (kt % 3) * B_STG;
        #pragma unroll
        for (int k16 = 0; k16 < 2; k16++) {
            uint32_t acol = kt * 64 + k16 * 32 + a_cb;
            uint32_t bcol = k16 * 32 + b_cb;
            uint32_t ah[4][4], bh[4][2];
            #pragma unroll
            for (int mf = 0; mf < 4; mf++)
                ldm4(ah[mf], Abase + (a_row + mf * 16) * A_ROWB + acol);
            #pragma unroll
            for (int nfp = 0; nfp < 2; nfp++) {
                uint32_t r4[4];
                ldm4(r4, bS + (b_row + nfp * 16) * B_ROWB + bcol);
                bh[nfp * 2 + 0][0] = r4[0]; bh[nfp * 2 + 0][1] = r4[1];
                bh[nfp * 2 + 1][0] = r4[2]; bh[nfp * 2 + 1][1] = r4[3];
            }
            #pragma unroll
            for (int mf = 0; mf < 4; mf++)
                #pragma unroll
                for (int nf = 0; nf < 4; nf++)
                    mma_f16(acc[mf][nf], ah[mf], bh[nf]);
        }
    }

    // epilogue: 64 rows x warp's 32 cols, + bias3 + residual
    #pragma unroll
    for (int mf = 0; mf < 4; mf++) {
        #pragma unroll
        for (int hf = 0; hf < 2; hf++) {
            int r = mf * 16 + hf * 8 + (lane >> 2);
            int mrow = mt * 64 + r;
            float bv = bias[b * C_ + mrow];
            long base = ((long)b * C_ + mrow) * N_ + (long)nt * 256;
            float* dst = outO + base;
            const float* rp = resid + base;
            #pragma unroll
            for (int nf = 0; nf < 4; nf++) {
                int n = wn + nf * 8 + 2 * (lane & 3);
                float2 rv = *(const float2*)&rp[n];
                float2 o;
                o.x = acc[mf][nf][hf * 2 + 0] + bv + rv.x;
                o.y = acc[mf][nf][hf * 2 + 1] + bv + rv.y;
                *(float2*)&dst[n] = o;
            }
        }
    }
}

// ============================================================
// host launch
// ============================================================
extern "C" void kernel_launch(void* const* d_in, const int* in_sizes, int n_in,
                              void* d_out, int out_size) {
    const float* x    = (const float*)d_in[0];
    const float* gnw  = (const float*)d_in[1];
    const float* gnb  = (const float*)d_in[2];
    const float* qkvW = (const float*)d_in[3];
    const float* ow   = (const float*)d_in[4];
    const float* ob   = (const float*)d_in[5];
    float* out = (float*)d_out;

    float* pBias3;
    __half *pXT, *pW3;
    cudaGetSymbolAddress((void**)&pBias3, d_bias3);
    cudaGetSymbolAddress((void**)&pXT, d_xT);
    cudaGetSymbolAddress((void**)&pW3, d_W3);

    cudaFuncSetAttribute(kv_sim, cudaFuncAttributeMaxDynamicSharedMemorySize, KV_SMEM);
    cudaFuncSetAttribute(gemm_out, cudaFuncAttributeMaxDynamicSharedMemorySize, KV_SMEM);

    tconv_stats<<<dim3(1024, 4, 4), dim3(32, 8)>>>(x, pXT);
    gn_stats2<<<16, 256>>>(gnw, gnb);
    build_wp<<<dim3(768, 4), 256>>>(qkvW);

    kv_sim<<<dim3(8, 128, 4), 256, KV_SMEM>>>();
    krow_final<<<32, 1024>>>();
    sim_part2<<<dim3(32, 8), 1024>>>();
    sim_final<<<32, 1024>>>();
    build_w23<<<dim3(256, 4), 256>>>(ow, ob);

    gemm_out<<<dim3(4, 128, 4), 256, KV_SMEM>>>(pW3, pXT, pBias3, x, out);
}

// round 15
// speedup vs baseline: 1.1848x; 1.0070x over previous
#include <cuda_runtime.h>
#include <cuda_fp16.h>
#include <cstdint>

// Problem constants
static constexpr int B_ = 4;
static constexpr int C_ = 256;
static constexpr int N_ = 32768;     // 32*32*32
static constexpr int H_ = 8;
static constexpr int NCH = 128;      // n-chunks of 256

// ---------------- device scratch (no allocations allowed) ----------------
__device__ __half d_xT[(long)B_ * N_ * C_];        // xT [b][n][c] fp16
__device__ __half d_Wp[B_ * 768 * C_];             // GN-folded qkv weight fp16
__device__ float d_biasp[B_ * 768];
__device__ __half d_W3[B_ * C_ * C_];              // W2 @ Wq' fp16
__device__ float d_bias3[B_ * C_];
__device__ float2 d_gpart[16 * 1024];              // GN partials (sum, sumsq)
__device__ float d_scale[B_ * C_];
__device__ float d_shift[B_ * C_];
__device__ float d_cs[(long)B_ * H_ * NCH * 32];   // per-chunk sumexp (scaled)
__device__ float d_simpart[(long)B_ * H_ * NCH * 1024];
__device__ float d_sp2[(long)B_ * H_ * 8 * 1024];  // second-level partials
__device__ float d_s[B_ * H_ * 32];                // row sumexp (scaled)
__device__ float d_sim[B_ * H_ * 1024];

// ---------------- PTX helpers ----------------
__device__ __forceinline__ uint32_t smem_u32(const void* p) {
    uint32_t a;
    asm("{ .reg .u64 t; cvta.to.shared.u64 t, %1; cvt.u32.u64 %0, t; }" : "=r"(a) : "l"(p));
    return a;
}
#define CP16(dst, src) asm volatile("cp.async.cg.shared.global [%0], [%1], 16;" :: "r"(dst), "l"(src))
#define CP_COMMIT()    asm volatile("cp.async.commit_group;")

__device__ __forceinline__ void ldm4(uint32_t* r, uint32_t addr) {
    asm volatile("ldmatrix.sync.aligned.m8n8.x4.shared.b16 {%0,%1,%2,%3}, [%4];"
        : "=r"(r[0]), "=r"(r[1]), "=r"(r[2]), "=r"(r[3]) : "r"(addr));
}
__device__ __forceinline__ void mma_f16(float* d, const uint32_t* a, const uint32_t* b) {
    asm volatile(
        "mma.sync.aligned.m16n8k16.row.col.f32.f16.f16.f32 "
        "{%0,%1,%2,%3}, {%4,%5,%6,%7}, {%8,%9}, {%0,%1,%2,%3};"
        : "+f"(d[0]), "+f"(d[1]), "+f"(d[2]), "+f"(d[3])
        : "r"(a[0]), "r"(a[1]), "r"(a[2]), "r"(a[3]), "r"(b[0]), "r"(b[1]));
}

// ============================================================
// Fused: x transpose->fp16 xT + GN partial stats.
// ============================================================
__global__ void tconv_stats(const float* __restrict__ x, __half* __restrict__ dst) {
    __shared__ float t[64][33];
    __shared__ float rs[256], rss[256];
    int n0 = blockIdx.x * 32, c0 = blockIdx.y * 64, b = blockIdx.z;
    const float* s = x + (long)b * C_ * N_;
    int tx = threadIdx.x, ty = threadIdx.y;
    int tid = ty * 32 + tx;
    float sum = 0.f, ss = 0.f;
    #pragma unroll
    for (int i = 0; i < 8; i++) {
        int cl = ty + i * 8;
        float v = s[(long)(c0 + cl) * N_ + n0 + tx];
        t[cl][tx] = v;
        sum += v; ss += v * v;
    }
    rs[tid] = sum; rss[tid] = ss;
    __syncthreads();
    __half* ph = dst + (long)b * N_ * C_;
    #pragma unroll
    for (int i = 0; i < 4; i++) {
        int nl = ty + i * 8;
        __half2 h = __floats2half2_rn(t[2 * tx][nl], t[2 * tx + 1][nl]);
        *(__half2*)&ph[(long)(n0 + nl) * C_ + c0 + 2 * tx] = h;
    }
    for (int st = 128; st > 0; st >>= 1) {
        if (tid < st) { rs[tid] += rs[tid + st]; rss[tid] += rss[tid + st]; }
        __syncthreads();
    }
    if (tid == 0)
        d_gpart[(b * 4 + blockIdx.y) * 1024 + blockIdx.x] = make_float2(rs[0], rss[0]);
}

__global__ void gn_stats2(const float* __restrict__ gnw, const float* __restrict__ gnb) {
    int bg = blockIdx.x, tid = threadIdx.x;
    __shared__ float rs[256], rss[256];
    float s = 0.f, ss = 0.f;
    for (int i = tid; i < 1024; i += 256) {
        float2 p = d_gpart[bg * 1024 + i];
        s += p.x; ss += p.y;
    }
    rs[tid] = s; rss[tid] = ss;
    __syncthreads();
    for (int st = 128; st > 0; st >>= 1) {
        if (tid < st) { rs[tid] += rs[tid + st]; rss[tid] += rss[tid + st]; }
        __syncthreads();
    }
    if (tid < 64) {
        float inv = 1.0f / (float)(64L * N_);
        float mean = rs[0] * inv;
        float var = rss[0] * inv - mean * mean;
        float rstd = rsqrtf(var + 1e-5f);
        int b = bg >> 2, g = bg & 3;
        int c = g * 64 + tid;
        float sc = rstd * gnw[c];
        d_scale[b * C_ + c] = sc;
        d_shift[b * C_ + c] = gnb[c] - mean * sc;
    }
}

__global__ void build_wp(const float* __restrict__ W) {
    int o = blockIdx.x, b = blockIdx.y, c = threadIdx.x;
    float w = W[o * C_ + c];
    d_Wp[((long)b * 768 + o) * C_ + c] = __float2half_rn(w * d_scale[b * C_ + c]);
    __shared__ float red[256];
    red[c] = w * d_shift[b * C_ + c];
    __syncthreads();
    for (int st = 128; st > 0; st >>= 1) {
        if (c < st) red[c] += red[c + st];
        __syncthreads();
    }
    if (c == 0) d_biasp[b * 768 + o] = red[0];
}

// ============================================================
// Shared tile geometry for barrier-free M=64 x N=256 GEMMs.
// ============================================================
static constexpr int A_ROWB = 528;                 // 256 halves + 16B pad
static constexpr int A_BYTES = 64 * A_ROWB;        // 33792
static constexpr int B_ROWB = 80;                  // 32 halves + 16B pad
static constexpr int B_STG = 32 * B_ROWB;          // 2560 per warp per stage
static constexpr int B_WARP = 3 * B_STG;           // 7680
static constexpr int KV_SMEM = A_BYTES + 8 * B_WARP;   // 95232
static constexpr int XROW = 528;
static constexpr float EXPSC = 0.0625f;            // fp16 exp storage scale (cancels in sim/S)

// ============================================================
// kv_sim: fused k/v GEMM + scaled-exp + sim partial (no max pass).
// grid (h=8, nt=128, b=4), block 256 (8 warps). Barrier-free mainloop.
// ============================================================
__global__ void __launch_bounds__(256, 2) kv_sim() {
    extern __shared__ char smem[];
    uint32_t sb = smem_u32(smem);
    int tid = threadIdx.x, lane = tid & 31, wrp = tid >> 5;
    int h = blockIdx.x, nt = blockIdx.y, b = blockIdx.z;
    int wn = wrp * 32;

    const __half* Ak = d_Wp + ((long)b * 768 + 256 + h * 32) * 256;
    const __half* Av = d_Wp + ((long)b * 768 + 512 + h * 32) * 256;
    const __half* Bx = d_xT + ((long)b * N_ + nt * 256) * 256;

    uint32_t Abase = sb;
    uint32_t wb = sb + A_BYTES + wrp * B_WARP;

    #pragma unroll
    for (int it = 0; it < 8; it++) {
        int idx = tid + it * 256;
        int row = idx >> 5, seg = idx & 31;
        const __half* src = (row < 32 ? Ak + (long)row * 256
                                      : Av + (long)(row - 32) * 256) + seg * 8;
        CP16(Abase + row * A_ROWB + seg * 16, src);
    }
    CP_COMMIT();

    auto loadB = [&](int kt) {
        uint32_t dst = wb + (kt % 3) * B_STG;
        int k0 = kt * 32;
        #pragma unroll
        for (int l = 0; l < 4; l++) {
            int idx = lane + l * 32;
            int row = idx >> 2, seg = idx & 3;
            CP16(dst + row * B_ROWB + seg * 16,
                 Bx + (long)(wn + row) * 256 + k0 + seg * 8);
        }
        CP_COMMIT();
    };
    loadB(0); loadB(1);

    float acc[4][4][4];
    #pragma unroll
    for (int i = 0; i < 4; i++)
        #pragma unroll
        for (int j = 0; j < 4; j++)
            #pragma unroll
            for (int e = 0; e < 4; e++) acc[i][j][e] = 0.f;

    int quad = lane >> 3, qr = lane & 7;
    int a_row = (quad & 1) * 8 + qr;
    int a_cb = (quad >> 1) * 16;
    int b_row = ((lane >> 4) & 1) * 8 + (lane & 7);
    int b_cb = ((lane >> 3) & 1) * 16;

    #pragma unroll 1
    for (int kt = 0; kt < 8; kt++) {
        if (kt < 7) { asm volatile("cp.async.wait_group 1;"); }
        else        { asm volatile("cp.async.wait_group 0;"); }
        if (kt == 0) __syncthreads();
        else         __syncwarp();
        if (kt + 2 < 8) loadB(kt + 2);

        uint32_t bS = wb + (kt % 3) * B_STG;
        #pragma unroll
        for (int k16 = 0; k16 < 2; k16++) {
            uint32_t acol = kt * 64 + k16 * 32 + a_cb;
            uint32_t bcol = k16 * 32 + b_cb;
            uint32_t ah[4][4], bh[4][2];
            #pragma unroll
            for (int mf = 0; mf < 4; mf++)
                ldm4(ah[mf], Abase + (a_row + mf * 16) * A_ROWB + acol);
            #pragma unroll
            for (int nfp = 0; nfp < 2; nfp++) {
                uint32_t r4[4];
                ldm4(r4, bS + (b_row + nfp * 16) * B_ROWB + bcol);
                bh[nfp * 2 + 0][0] = r4[0]; bh[nfp * 2 + 0][1] = r4[1];
                bh[nfp * 2 + 1][0] = r4[2]; bh[nfp * 2 + 1][1] = r4[3];
            }
            #pragma unroll
            for (int mf = 0; mf < 4; mf++)
                #pragma unroll
                for (int nf = 0; nf < 4; nf++)
                    mma_f16(acc[mf][nf], ah[mf], bh[nf]);
        }
    }
    __syncthreads();

    // ---- overlay layout ----
    char* kx = smem;                       // 32 x 528
    char* vx = smem + 16896;               // 32 x 528
    float* red = (float*)(smem + 33792);   // 8 x 1024 floats
    float* sm_s = (float*)(smem + 66560);  // [32][8]

    long bhc = ((long)(b * H_ + h) * NCH + nt);
    const float* bp = d_biasp + b * 768;

    // single pass: k rows (mf<2) -> scaled exp fp16 + sumexp; v rows -> vx fp16
    #pragma unroll
    for (int mf = 0; mf < 4; mf++) {
        #pragma unroll
        for (int hf = 0; hf < 2; hf++) {
            int r = mf * 16 + hf * 8 + (lane >> 2);
            if (mf < 2) {
                float bv = bp[256 + h * 32 + r];
                float ssum = 0.f;
                #pragma unroll
                for (int nf = 0; nf < 4; nf++) {
                    int c = wn + nf * 8 + 2 * (lane & 3);
                    float e0 = __expf(acc[mf][nf][hf * 2] + bv) * EXPSC;
                    float e1 = __expf(acc[mf][nf][hf * 2 + 1] + bv) * EXPSC;
                    ssum += e0 + e1;
                    *(__half2*)(kx + r * XROW + c * 2) = __floats2half2_rn(e0, e1);
                }
                ssum += __shfl_xor_sync(0xffffffffu, ssum, 1);
                ssum += __shfl_xor_sync(0xffffffffu, ssum, 2);
                if ((lane & 3) == 0) sm_s[r * 8 + wrp] = ssum;
            } else {
                int e = r - 32;
                float bv = bp[512 + h * 32 + e];
                #pragma unroll
                for (int nf = 0; nf < 4; nf++) {
                    int c = wn + nf * 8 + 2 * (lane & 3);
                    *(__half2*)(vx + e * XROW + c * 2) =
                        __floats2half2_rn(acc[mf][nf][hf * 2] + bv,
                                          acc[mf][nf][hf * 2 + 1] + bv);
                }
            }
        }
    }
    __syncthreads();
    if (tid < 32) {
        float s = 0.f;
        #pragma unroll
        for (int ww = 0; ww < 8; ww++) s += sm_s[tid * 8 + ww];
        d_cs[bhc * 32 + tid] = s;
    }

    // phase 2: simpart = expk(32x256) @ v(32x256)^T, warp = 64-wide K slice
    float acc2[2][4][4];
    #pragma unroll
    for (int i = 0; i < 2; i++)
        #pragma unroll
        for (int j = 0; j < 4; j++)
            #pragma unroll
            for (int e = 0; e < 4; e++) acc2[i][j][e] = 0.f;

    uint32_t kxu = smem_u32(kx), vxu = smem_u32(vx);
    int a2_row = (quad & 1) * 8 + qr;
    int b2_row = ((lane >> 4) & 1) * 8 + (lane & 7);
    uint32_t colb = wrp * 64;
    #pragma unroll
    for (int k16 = 0; k16 < 2; k16++) {
        uint32_t ac = colb + k16 * 32 + a_cb;
        uint32_t bc = colb + k16 * 32 + b_cb;
        uint32_t af[2][4], bf[4][2];
        #pragma unroll
        for (int mf = 0; mf < 2; mf++)
            ldm4(af[mf], kxu + (a2_row + mf * 16) * XROW + ac);
        #pragma unroll
        for (int nfp = 0; nfp < 2; nfp++) {
            uint32_t r4[4];
            ldm4(r4, vxu + (b2_row + nfp * 16) * XROW + bc);
            bf[nfp * 2 + 0][0] = r4[0]; bf[nfp * 2 + 0][1] = r4[1];
            bf[nfp * 2 + 1][0] = r4[2]; bf[nfp * 2 + 1][1] = r4[3];
        }
        #pragma unroll
        for (int mf = 0; mf < 2; mf++)
            #pragma unroll
            for (int nf = 0; nf < 4; nf++)
                mma_f16(acc2[mf][nf], af[mf], bf[nf]);
    }

    float* my = red + wrp * 1024;
    #pragma unroll
    for (int mf = 0; mf < 2; mf++) {
        int r = mf * 16 + (lane >> 2);
        #pragma unroll
        for (int nf = 0; nf < 4; nf++) {
            int c = nf * 8 + 2 * (lane & 3);
            my[r * 32 + c]           = acc2[mf][nf][0];
            my[r * 32 + c + 1]       = acc2[mf][nf][1];
            my[(r + 8) * 32 + c]     = acc2[mf][nf][2];
            my[(r + 8) * 32 + c + 1] = acc2[mf][nf][3];
        }
    }
    __syncthreads();
    float* outp = d_simpart + bhc * 1024;
    for (int i = tid; i < 1024; i += 256) {
        float s = 0.f;
        #pragma unroll
        for (int ww = 0; ww < 8; ww++) s += red[ww * 1024 + i];
        outp[i] = s;
    }
}

// ============================================================
// sim_part2: plain 16-chunk sums. grid (32 bh, 8 p), block 1024.
// ============================================================
__global__ void sim_part2() {
    int bh = blockIdx.x, p = blockIdx.y, i = threadIdx.x;
    const float* base = d_simpart + (long)bh * NCH * 1024;
    float acc = 0.f;
    #pragma unroll 4
    for (int c = 0; c < 16; c++)
        acc += base[(long)(p * 16 + c) * 1024 + i];
    d_sp2[((long)bh * 8 + p) * 1024 + i] = acc;
}

// sim_final: merge 8 partials + S = sum of chunk sumexps.
__global__ void sim_final() {
    int bh = blockIdx.x, i = threadIdx.x;
    float s = 0.f;
    #pragma unroll
    for (int p = 0; p < 8; p++)
        s += d_sp2[((long)bh * 8 + p) * 1024 + i];
    d_sim[bh * 1024 + i] = s;
    if (i < 32) {
        float S = 0.f;
        const float* csp = d_cs + (long)bh * NCH * 32;
        #pragma unroll 8
        for (int ch = 0; ch < NCH; ch++) S += csp[ch * 32 + i];
        d_s[bh * 32 + i] = S;
    }
}

// ============================================================
// build_w23: W2 row (in smem) -> W3 row + bias3. grid (256, 4), 256 thr.
// ============================================================
__global__ void build_w23(const float* __restrict__ OW, const float* __restrict__ ob) {
    int o = blockIdx.x, b = blockIdx.y, cp = threadIdx.x;
    int h = cp >> 5, d = cp & 31;
    int bh = b * 8 + h;
    __shared__ float w2row[256];
    __shared__ float red[256];
    const float* simp = d_sim + (long)(bh * 32 + d) * 32;
    const float* owp = OW + o * C_ + h * 32;
    float s = 0.f;
    #pragma unroll
    for (int e = 0; e < 32; e++) s += owp[e] * simp[e];
    s *= 1.0f / d_s[bh * 32 + d];
    w2row[cp] = s;
    red[cp] = s * d_biasp[b * 768 + cp];
    __syncthreads();
    float acc = 0.f;
    const __half* wq = d_Wp + (long)b * 768 * C_;
    #pragma unroll 8
    for (int e = 0; e < 256; e++)
        acc += w2row[e] * __half2float(wq[(long)e * C_ + cp]);
    d_W3[((long)b * C_ + o) * C_ + cp] = __float2half_rn(acc);
    for (int st = 128; st > 0; st >>= 1) {
        if (cp < st) red[cp] += red[cp + st];
        __syncthreads();
    }
    if (cp == 0) d_bias3[b * C_ + o] = ob[o] + red[0];
}

// ============================================================
// gemm_out (barrier-free): out = W3 @ xT^T + bias3 + x.
// grid (mt=4, nt=128, b=4), block 256. M=64, N=256, same ring as kv_sim.
// ============================================================
__global__ void __launch_bounds__(256, 2) gemm_out(
    const __half* __restrict__ W3, const __half* __restrict__ XT,
    const float* __restrict__ bias, const float* __restrict__ resid,
    float* __restrict__ outO)
{
    extern __shared__ char smem[];
    uint32_t sb = smem_u32(smem);
    int tid = threadIdx.x, lane = tid & 31, wrp = tid >> 5;
    int mt = blockIdx.x, nt = blockIdx.y, b = blockIdx.z;
    int wn = wrp * 32;

    const __half* A = W3 + (long)b * C_ * C_ + (long)mt * 64 * 256;
    const __half* Bx = XT + ((long)b * N_ + nt * 256) * 256;

    uint32_t Abase = sb;
    uint32_t wb = sb + A_BYTES + wrp * B_WARP;

    #pragma unroll
    for (int it = 0; it < 8; it++) {
        int idx = tid + it * 256;
        int row = idx >> 5, seg = idx & 31;
        CP16(Abase + row * A_ROWB + seg * 16, A + (long)row * 256 + seg * 8);
    }
    CP_COMMIT();

    auto loadB = [&](int kt) {
        uint32_t dst = wb + (kt % 3) * B_STG;
        int k0 = kt * 32;
        #pragma unroll
        for (int l = 0; l < 4; l++) {
            int idx = lane + l * 32;
            int row = idx >> 2, seg = idx & 3;
            CP16(dst + row * B_ROWB + seg * 16,
                 Bx + (long)(wn + row) * 256 + k0 + seg * 8);
        }
        CP_COMMIT();
    };
    loadB(0); loadB(1);

    float acc[4][4][4];
    #pragma unroll
    for (int i = 0; i < 4; i++)
        #pragma unroll
        for (int j = 0; j < 4; j++)
            #pragma unroll
            for (int e = 0; e < 4; e++) acc[i][j][e] = 0.f;

    int quad = lane >> 3, qr = lane & 7;
    int a_row = (quad & 1) * 8 + qr;
    int a_cb = (quad >> 1) * 16;
    int b_row = ((lane >> 4) & 1) * 8 + (lane & 7);
    int b_cb = ((lane >> 3) & 1) * 16;

    #pragma unroll 1
    for (int kt = 0; kt < 8; kt++) {
        if (kt < 7) { asm volatile("cp.async.wait_group 1;"); }
        else        { asm volatile("cp.async.wait_group 0;"); }
        if (kt == 0) __syncthreads();
        else         __syncwarp();
        if (kt + 2 < 8) loadB(kt + 2);

        uint32_t bS = wb + (kt % 3) * B_STG;
        #pragma unroll
        for (int k16 = 0; k16 < 2; k16++) {
            uint32_t acol = kt * 64 + k16 * 32 + a_cb;
            uint32_t bcol = k16 * 32 + b_cb;
            uint32_t ah[4][4], bh[4][2];
            #pragma unroll
            for (int mf = 0; mf < 4; mf++)
                ldm4(ah[mf], Abase + (a_row + mf * 16) * A_ROWB + acol);
            #pragma unroll
            for (int nfp = 0; nfp < 2; nfp++) {
                uint32_t r4[4];
                ldm4(r4, bS + (b_row + nfp * 16) * B_ROWB + bcol);
                bh[nfp * 2 + 0][0] = r4[0]; bh[nfp * 2 + 0][1] = r4[1];
                bh[nfp * 2 + 1][0] = r4[2]; bh[nfp * 2 + 1][1] = r4[3];
            }
            #pragma unroll
            for (int mf = 0; mf < 4; mf++)
                #pragma unroll
                for (int nf = 0; nf < 4; nf++)
                    mma_f16(acc[mf][nf], ah[mf], bh[nf]);
        }
    }

    // epilogue: 64 rows x warp's 32 cols, + bias3 + residual
    #pragma unroll
    for (int mf = 0; mf < 4; mf++) {
        #pragma unroll
        for (int hf = 0; hf < 2; hf++) {
            int r = mf * 16 + hf * 8 + (lane >> 2);
            int mrow = mt * 64 + r;
            float bv = bias[b * C_ + mrow];
            long base = ((long)b * C_ + mrow) * N_ + (long)nt * 256;
            float* dst = outO + base;
            const float* rp = resid + base;
            #pragma unroll
            for (int nf = 0; nf < 4; nf++) {
                int n = wn + nf * 8 + 2 * (lane & 3);
                float2 rv = *(const float2*)&rp[n];
                float2 o;
                o.x = acc[mf][nf][hf * 2 + 0] + bv + rv.x;
                o.y = acc[mf][nf][hf * 2 + 1] + bv + rv.y;
                *(float2*)&dst[n] = o;
            }
        }
    }
}

// ============================================================
// host launch
// ============================================================
extern "C" void kernel_launch(void* const* d_in, const int* in_sizes, int n_in,
                              void* d_out, int out_size) {
    const float* x    = (const float*)d_in[0];
    const float* gnw  = (const float*)d_in[1];
    const float* gnb  = (const float*)d_in[2];
    const float* qkvW = (const float*)d_in[3];
    const float* ow   = (const float*)d_in[4];
    const float* ob   = (const float*)d_in[5];
    float* out = (float*)d_out;

    float* pBias3;
    __half *pXT, *pW3;
    cudaGetSymbolAddress((void**)&pBias3, d_bias3);
    cudaGetSymbolAddress((void**)&pXT, d_xT);
    cudaGetSymbolAddress((void**)&pW3, d_W3);

    cudaFuncSetAttribute(kv_sim, cudaFuncAttributeMaxDynamicSharedMemorySize, KV_SMEM);
    cudaFuncSetAttribute(gemm_out, cudaFuncAttributeMaxDynamicSharedMemorySize, KV_SMEM);

    tconv_stats<<<dim3(1024, 4, 4), dim3(32, 8)>>>(x, pXT);
    gn_stats2<<<16, 256>>>(gnw, gnb);
    build_wp<<<dim3(768, 4), 256>>>(qkvW);

    kv_sim<<<dim3(8, 128, 4), 256, KV_SMEM>>>();
    sim_part2<<<dim3(32, 8), 1024>>>();
    sim_final<<<32, 1024>>>();
    build_w23<<<dim3(256, 4), 256>>>(ow, ob);

    gemm_out<<<dim3(4, 128, 4), 256, KV_SMEM>>>(pW3, pXT, pBias3, x, out);
}

// round 17
// speedup vs baseline: 1.2404x; 1.0470x over previous
#include <cuda_runtime.h>
#include <cuda_fp16.h>
#include <cstdint>

// Problem constants
static constexpr int B_ = 4;
static constexpr int C_ = 256;
static constexpr int N_ = 32768;     // 32*32*32
static constexpr int H_ = 8;
static constexpr int NCH = 128;      // n-chunks of 256

// ---------------- device scratch (no allocations allowed) ----------------
__device__ __half d_xT[(long)B_ * N_ * C_];        // xT [b][n][c] fp16
__device__ __half d_Wp[B_ * 768 * C_];             // GN-folded qkv weight fp16
__device__ float d_biasp[B_ * 768];
__device__ __half d_W3[B_ * C_ * C_];              // W2 @ Wq' + I  (fp16)
__device__ float d_bias3[B_ * C_];
__device__ float2 d_gpart[16 * 1024];              // GN partials (sum, sumsq)
__device__ float d_scale[B_ * C_];
__device__ float d_shift[B_ * C_];
__device__ float d_cs[(long)B_ * H_ * NCH * 32];   // per-chunk sumexp (scaled)
__device__ float d_simpart[(long)B_ * H_ * NCH * 1024];
__device__ float d_sp2[(long)B_ * H_ * 8 * 1024];  // second-level partials
__device__ float d_s[B_ * H_ * 32];                // row sumexp (scaled)
__device__ float d_sim[B_ * H_ * 1024];

// ---------------- PTX helpers ----------------
__device__ __forceinline__ uint32_t smem_u32(const void* p) {
    uint32_t a;
    asm("{ .reg .u64 t; cvta.to.shared.u64 t, %1; cvt.u32.u64 %0, t; }" : "=r"(a) : "l"(p));
    return a;
}
#define CP16(dst, src) asm volatile("cp.async.cg.shared.global [%0], [%1], 16;" :: "r"(dst), "l"(src))
#define CP_COMMIT()    asm volatile("cp.async.commit_group;")

__device__ __forceinline__ void ldm4(uint32_t* r, uint32_t addr) {
    asm volatile("ldmatrix.sync.aligned.m8n8.x4.shared.b16 {%0,%1,%2,%3}, [%4];"
        : "=r"(r[0]), "=r"(r[1]), "=r"(r[2]), "=r"(r[3]) : "r"(addr));
}
__device__ __forceinline__ void mma_f16(float* d, const uint32_t* a, const uint32_t* b) {
    asm volatile(
        "mma.sync.aligned.m16n8k16.row.col.f32.f16.f16.f32 "
        "{%0,%1,%2,%3}, {%4,%5,%6,%7}, {%8,%9}, {%0,%1,%2,%3};"
        : "+f"(d[0]), "+f"(d[1]), "+f"(d[2]), "+f"(d[3])
        : "r"(a[0]), "r"(a[1]), "r"(a[2]), "r"(a[3]), "r"(b[0]), "r"(b[1]));
}

// ============================================================
// Fused: x transpose->fp16 xT + GN partial stats.
// ============================================================
__global__ void tconv_stats(const float* __restrict__ x, __half* __restrict__ dst) {
    __shared__ float t[64][33];
    __shared__ float rs[256], rss[256];
    int n0 = blockIdx.x * 32, c0 = blockIdx.y * 64, b = blockIdx.z;
    const float* s = x + (long)b * C_ * N_;
    int tx = threadIdx.x, ty = threadIdx.y;
    int tid = ty * 32 + tx;
    float sum = 0.f, ss = 0.f;
    #pragma unroll
    for (int i = 0; i < 8; i++) {
        int cl = ty + i * 8;
        float v = s[(long)(c0 + cl) * N_ + n0 + tx];
        t[cl][tx] = v;
        sum += v; ss += v * v;
    }
    rs[tid] = sum; rss[tid] = ss;
    __syncthreads();
    __half* ph = dst + (long)b * N_ * C_;
    #pragma unroll
    for (int i = 0; i < 4; i++) {
        int nl = ty + i * 8;
        __half2 h = __floats2half2_rn(t[2 * tx][nl], t[2 * tx + 1][nl]);
        *(__half2*)&ph[(long)(n0 + nl) * C_ + c0 + 2 * tx] = h;
    }
    for (int st = 128; st > 0; st >>= 1) {
        if (tid < st) { rs[tid] += rs[tid + st]; rss[tid] += rss[tid + st]; }
        __syncthreads();
    }
    if (tid == 0)
        d_gpart[(b * 4 + blockIdx.y) * 1024 + blockIdx.x] = make_float2(rs[0], rss[0]);
}

__global__ void gn_stats2(const float* __restrict__ gnw, const float* __restrict__ gnb) {
    int bg = blockIdx.x, tid = threadIdx.x;
    __shared__ float rs[256], rss[256];
    float s = 0.f, ss = 0.f;
    for (int i = tid; i < 1024; i += 256) {
        float2 p = d_gpart[bg * 1024 + i];
        s += p.x; ss += p.y;
    }
    rs[tid] = s; rss[tid] = ss;
    __syncthreads();
    for (int st = 128; st > 0; st >>= 1) {
        if (tid < st) { rs[tid] += rs[tid + st]; rss[tid] += rss[tid + st]; }
        __syncthreads();
    }
    if (tid < 64) {
        float inv = 1.0f / (float)(64L * N_);
        float mean = rs[0] * inv;
        float var = rss[0] * inv - mean * mean;
        float rstd = rsqrtf(var + 1e-5f);
        int b = bg >> 2, g = bg & 3;
        int c = g * 64 + tid;
        float sc = rstd * gnw[c];
        d_scale[b * C_ + c] = sc;
        d_shift[b * C_ + c] = gnb[c] - mean * sc;
    }
}

__global__ void build_wp(const float* __restrict__ W) {
    int o = blockIdx.x, b = blockIdx.y, c = threadIdx.x;
    float w = W[o * C_ + c];
    d_Wp[((long)b * 768 + o) * C_ + c] = __float2half_rn(w * d_scale[b * C_ + c]);
    __shared__ float red[256];
    red[c] = w * d_shift[b * C_ + c];
    __syncthreads();
    for (int st = 128; st > 0; st >>= 1) {
        if (c < st) red[c] += red[c + st];
        __syncthreads();
    }
    if (c == 0) d_biasp[b * 768 + o] = red[0];
}

// ============================================================
// Shared tile geometry for barrier-free M=64 x N=256 GEMMs.
// ============================================================
static constexpr int A_ROWB = 528;                 // 256 halves + 16B pad
static constexpr int A_BYTES = 64 * A_ROWB;        // 33792
static constexpr int B_ROWB = 80;                  // 32 halves + 16B pad
static constexpr int B_STG = 32 * B_ROWB;          // 2560 per warp per stage
static constexpr int B_WARP = 3 * B_STG;           // 7680
static constexpr int KV_SMEM = A_BYTES + 8 * B_WARP;   // 95232
static constexpr int XROW = 528;
static constexpr float EXPSC = 0.0625f;            // fp16 exp storage scale (cancels in sim/S)

// ============================================================
// kv_sim: fused k/v GEMM + scaled-exp + sim partial (no max pass).
// grid (h=8, nt=128, b=4), block 256 (8 warps). Barrier-free mainloop.
// ============================================================
__global__ void __launch_bounds__(256, 2) kv_sim() {
    extern __shared__ char smem[];
    uint32_t sb = smem_u32(smem);
    int tid = threadIdx.x, lane = tid & 31, wrp = tid >> 5;
    int h = blockIdx.x, nt = blockIdx.y, b = blockIdx.z;
    int wn = wrp * 32;

    const __half* Ak = d_Wp + ((long)b * 768 + 256 + h * 32) * 256;
    const __half* Av = d_Wp + ((long)b * 768 + 512 + h * 32) * 256;
    const __half* Bx = d_xT + ((long)b * N_ + nt * 256) * 256;

    uint32_t Abase = sb;
    uint32_t wb = sb + A_BYTES + wrp * B_WARP;

    #pragma unroll
    for (int it = 0; it < 8; it++) {
        int idx = tid + it * 256;
        int row = idx >> 5, seg = idx & 31;
        const __half* src = (row < 32 ? Ak + (long)row * 256
                                      : Av + (long)(row - 32) * 256) + seg * 8;
        CP16(Abase + row * A_ROWB + seg * 16, src);
    }
    CP_COMMIT();

    auto loadB = [&](int kt) {
        uint32_t dst = wb + (kt % 3) * B_STG;
        int k0 = kt * 32;
        #pragma unroll
        for (int l = 0; l < 4; l++) {
            int idx = lane + l * 32;
            int row = idx >> 2, seg = idx & 3;
            CP16(dst + row * B_ROWB + seg * 16,
                 Bx + (long)(wn + row) * 256 + k0 + seg * 8);
        }
        CP_COMMIT();
    };
    loadB(0); loadB(1);

    float acc[4][4][4];
    #pragma unroll
    for (int i = 0; i < 4; i++)
        #pragma unroll
        for (int j = 0; j < 4; j++)
            #pragma unroll
            for (int e = 0; e < 4; e++) acc[i][j][e] = 0.f;

    int quad = lane >> 3, qr = lane & 7;
    int a_row = (quad & 1) * 8 + qr;
    int a_cb = (quad >> 1) * 16;
    int b_row = ((lane >> 4) & 1) * 8 + (lane & 7);
    int b_cb = ((lane >> 3) & 1) * 16;

    #pragma unroll 1
    for (int kt = 0; kt < 8; kt++) {
        if (kt < 7) { asm volatile("cp.async.wait_group 1;"); }
        else        { asm volatile("cp.async.wait_group 0;"); }
        if (kt == 0) __syncthreads();
        else         __syncwarp();
        if (kt + 2 < 8) loadB(kt + 2);

        uint32_t bS = wb + (kt % 3) * B_STG;
        #pragma unroll
        for (int k16 = 0; k16 < 2; k16++) {
            uint32_t acol = kt * 64 + k16 * 32 + a_cb;
            uint32_t bcol = k16 * 32 + b_cb;
            uint32_t ah[4][4], bh[4][2];
            #pragma unroll
            for (int mf = 0; mf < 4; mf++)
                ldm4(ah[mf], Abase + (a_row + mf * 16) * A_ROWB + acol);
            #pragma unroll
            for (int nfp = 0; nfp < 2; nfp++) {
                uint32_t r4[4];
                ldm4(r4, bS + (b_row + nfp * 16) * B_ROWB + bcol);
                bh[nfp * 2 + 0][0] = r4[0]; bh[nfp * 2 + 0][1] = r4[1];
                bh[nfp * 2 + 1][0] = r4[2]; bh[nfp * 2 + 1][1] = r4[3];
            }
            #pragma unroll
            for (int mf = 0; mf < 4; mf++)
                #pragma unroll
                for (int nf = 0; nf < 4; nf++)
                    mma_f16(acc[mf][nf], ah[mf], bh[nf]);
        }
    }
    __syncthreads();

    // ---- overlay layout ----
    char* kx = smem;                       // 32 x 528
    char* vx = smem + 16896;               // 32 x 528
    float* red = (float*)(smem + 33792);   // 8 x 1024 floats
    float* sm_s = (float*)(smem + 66560);  // [32][8]

    long bhc = ((long)(b * H_ + h) * NCH + nt);
    const float* bp = d_biasp + b * 768;

    // single pass: k rows (mf<2) -> scaled exp fp16 + sumexp; v rows -> vx fp16
    #pragma unroll
    for (int mf = 0; mf < 4; mf++) {
        #pragma unroll
        for (int hf = 0; hf < 2; hf++) {
            int r = mf * 16 + hf * 8 + (lane >> 2);
            if (mf < 2) {
                float bv = bp[256 + h * 32 + r];
                float ssum = 0.f;
                #pragma unroll
                for (int nf = 0; nf < 4; nf++) {
                    int c = wn + nf * 8 + 2 * (lane & 3);
                    float e0 = __expf(acc[mf][nf][hf * 2] + bv) * EXPSC;
                    float e1 = __expf(acc[mf][nf][hf * 2 + 1] + bv) * EXPSC;
                    ssum += e0 + e1;
                    *(__half2*)(kx + r * XROW + c * 2) = __floats2half2_rn(e0, e1);
                }
                ssum += __shfl_xor_sync(0xffffffffu, ssum, 1);
                ssum += __shfl_xor_sync(0xffffffffu, ssum, 2);
                if ((lane & 3) == 0) sm_s[r * 8 + wrp] = ssum;
            } else {
                int e = r - 32;
                float bv = bp[512 + h * 32 + e];
                #pragma unroll
                for (int nf = 0; nf < 4; nf++) {
                    int c = wn + nf * 8 + 2 * (lane & 3);
                    *(__half2*)(vx + e * XROW + c * 2) =
                        __floats2half2_rn(acc[mf][nf][hf * 2] + bv,
                                          acc[mf][nf][hf * 2 + 1] + bv);
                }
            }
        }
    }
    __syncthreads();
    if (tid < 32) {
        float s = 0.f;
        #pragma unroll
        for (int ww = 0; ww < 8; ww++) s += sm_s[tid * 8 + ww];
        d_cs[bhc * 32 + tid] = s;
    }

    // phase 2: simpart = expk(32x256) @ v(32x256)^T, warp = 64-wide K slice
    float acc2[2][4][4];
    #pragma unroll
    for (int i = 0; i < 2; i++)
        #pragma unroll
        for (int j = 0; j < 4; j++)
            #pragma unroll
            for (int e = 0; e < 4; e++) acc2[i][j][e] = 0.f;

    uint32_t kxu = smem_u32(kx), vxu = smem_u32(vx);
    int a2_row = (quad & 1) * 8 + qr;
    int b2_row = ((lane >> 4) & 1) * 8 + (lane & 7);
    uint32_t colb = wrp * 64;
    #pragma unroll
    for (int k16 = 0; k16 < 2; k16++) {
        uint32_t ac = colb + k16 * 32 + a_cb;
        uint32_t bc = colb + k16 * 32 + b_cb;
        uint32_t af[2][4], bf[4][2];
        #pragma unroll
        for (int mf = 0; mf < 2; mf++)
            ldm4(af[mf], kxu + (a2_row + mf * 16) * XROW + ac);
        #pragma unroll
        for (int nfp = 0; nfp < 2; nfp++) {
            uint32_t r4[4];
            ldm4(r4, vxu + (b2_row + nfp * 16) * XROW + bc);
            bf[nfp * 2 + 0][0] = r4[0]; bf[nfp * 2 + 0][1] = r4[1];
            bf[nfp * 2 + 1][0] = r4[2]; bf[nfp * 2 + 1][1] = r4[3];
        }
        #pragma unroll
        for (int mf = 0; mf < 2; mf++)
            #pragma unroll
            for (int nf = 0; nf < 4; nf++)
                mma_f16(acc2[mf][nf], af[mf], bf[nf]);
    }

    float* my = red + wrp * 1024;
    #pragma unroll
    for (int mf = 0; mf < 2; mf++) {
        int r = mf * 16 + (lane >> 2);
        #pragma unroll
        for (int nf = 0; nf < 4; nf++) {
            int c = nf * 8 + 2 * (lane & 3);
            my[r * 32 + c]           = acc2[mf][nf][0];
            my[r * 32 + c + 1]       = acc2[mf][nf][1];
            my[(r + 8) * 32 + c]     = acc2[mf][nf][2];
            my[(r + 8) * 32 + c + 1] = acc2[mf][nf][3];
        }
    }
    __syncthreads();
    float* outp = d_simpart + bhc * 1024;
    for (int i = tid; i < 1024; i += 256) {
        float s = 0.f;
        #pragma unroll
        for (int ww = 0; ww < 8; ww++) s += red[ww * 1024 + i];
        outp[i] = s;
    }
}

// ============================================================
// sim_part2: plain 16-chunk sums. grid (32 bh, 8 p), block 1024.
// ============================================================
__global__ void sim_part2() {
    int bh = blockIdx.x, p = blockIdx.y, i = threadIdx.x;
    const float* base = d_simpart + (long)bh * NCH * 1024;
    float acc = 0.f;
    #pragma unroll 4
    for (int c = 0; c < 16; c++)
        acc += base[(long)(p * 16 + c) * 1024 + i];
    d_sp2[((long)bh * 8 + p) * 1024 + i] = acc;
}

// sim_final: merge 8 partials + S = sum of chunk sumexps.
__global__ void sim_final() {
    int bh = blockIdx.x, i = threadIdx.x;
    float s = 0.f;
    #pragma unroll
    for (int p = 0; p < 8; p++)
        s += d_sp2[((long)bh * 8 + p) * 1024 + i];
    d_sim[bh * 1024 + i] = s;
    if (i < 32) {
        float S = 0.f;
        const float* csp = d_cs + (long)bh * NCH * 32;
        #pragma unroll 8
        for (int ch = 0; ch < NCH; ch++) S += csp[ch * 32 + i];
        d_s[bh * 32 + i] = S;
    }
}

// ============================================================
// build_w23: W2 row (in smem) -> W3 row (+ I for residual) + bias3.
// grid (256, 4), 256 thr.
// ============================================================
__global__ void build_w23(const float* __restrict__ OW, const float* __restrict__ ob) {
    int o = blockIdx.x, b = blockIdx.y, cp = threadIdx.x;
    int h = cp >> 5, d = cp & 31;
    int bh = b * 8 + h;
    __shared__ float w2row[256];
    __shared__ float red[256];
    const float* simp = d_sim + (long)(bh * 32 + d) * 32;
    const float* owp = OW + o * C_ + h * 32;
    float s = 0.f;
    #pragma unroll
    for (int e = 0; e < 32; e++) s += owp[e] * simp[e];
    s *= 1.0f / d_s[bh * 32 + d];
    w2row[cp] = s;
    red[cp] = s * d_biasp[b * 768 + cp];
    __syncthreads();
    float acc = 0.f;
    const __half* wq = d_Wp + (long)b * 768 * C_;
    #pragma unroll 8
    for (int e = 0; e < 256; e++)
        acc += w2row[e] * __half2float(wq[(long)e * C_ + cp]);
    if (cp == o) acc += 1.0f;   // fold residual: W3' = W3 + I (xT is x in fp16)
    d_W3[((long)b * C_ + o) * C_ + cp] = __float2half_rn(acc);
    for (int st = 128; st > 0; st >>= 1) {
        if (cp < st) red[cp] += red[cp + st];
        __syncthreads();
    }
    if (cp == 0) d_bias3[b * C_ + o] = ob[o] + red[0];
}

// ============================================================
// gemm_out (barrier-free): out = (W3 + I) @ xT^T + bias3.
// grid (mt=4, nt=128, b=4), block 256. M=64, N=256, same ring as kv_sim.
// ============================================================
__global__ void __launch_bounds__(256, 2) gemm_out(
    const __half* __restrict__ W3, const __half* __restrict__ XT,
    const float* __restrict__ bias, float* __restrict__ outO)
{
    extern __shared__ char smem[];
    uint32_t sb = smem_u32(smem);
    int tid = threadIdx.x, lane = tid & 31, wrp = tid >> 5;
    int mt = blockIdx.x, nt = blockIdx.y, b = blockIdx.z;
    int wn = wrp * 32;

    const __half* A = W3 + (long)b * C_ * C_ + (long)mt * 64 * 256;
    const __half* Bx = XT + ((long)b * N_ + nt * 256) * 256;

    uint32_t Abase = sb;
    uint32_t wb = sb + A_BYTES + wrp * B_WARP;

    #pragma unroll
    for (int it = 0; it < 8; it++) {
        int idx = tid + it * 256;
        int row = idx >> 5, seg = idx & 31;
        CP16(Abase + row * A_ROWB + seg * 16, A + (long)row * 256 + seg * 8);
    }
    CP_COMMIT();

    auto loadB = [&](int kt) {
        uint32_t dst = wb + (kt % 3) * B_STG;
        int k0 = kt * 32;
        #pragma unroll
        for (int l = 0; l < 4; l++) {
            int idx = lane + l * 32;
            int row = idx >> 2, seg = idx & 3;
            CP16(dst + row * B_ROWB + seg * 16,
                 Bx + (long)(wn + row) * 256 + k0 + seg * 8);
        }
        CP_COMMIT();
    };
    loadB(0); loadB(1);

    float acc[4][4][4];
    #pragma unroll
    for (int i = 0; i < 4; i++)
        #pragma unroll
        for (int j = 0; j < 4; j++)
            #pragma unroll
            for (int e = 0; e < 4; e++) acc[i][j][e] = 0.f;

    int quad = lane >> 3, qr = lane & 7;
    int a_row = (quad & 1) * 8 + qr;
    int a_cb = (quad >> 1) * 16;
    int b_row = ((lane >> 4) & 1) * 8 + (lane & 7);
    int b_cb = ((lane >> 3) & 1) * 16;

    #pragma unroll 1
    for (int kt = 0; kt < 8; kt++) {
        if (kt < 7) { asm volatile("cp.async.wait_group 1;"); }
        else        { asm volatile("cp.async.wait_group 0;"); }
        if (kt == 0) __syncthreads();
        else         __syncwarp();
        if (kt + 2 < 8) loadB(kt + 2);

        uint32_t bS = wb + (kt % 3) * B_STG;
        #pragma unroll
        for (int k16 = 0; k16 < 2; k16++) {
            uint32_t acol = kt * 64 + k16 * 32 + a_cb;
            uint32_t bcol = k16 * 32 + b_cb;
            uint32_t ah[4][4], bh[4][2];
            #pragma unroll
            for (int mf = 0; mf < 4; mf++)
                ldm4(ah[mf], Abase + (a_row + mf * 16) * A_ROWB + acol);
            #pragma unroll
            for (int nfp = 0; nfp < 2; nfp++) {
                uint32_t r4[4];
                ldm4(r4, bS + (b_row + nfp * 16) * B_ROWB + bcol);
                bh[nfp * 2 + 0][0] = r4[0]; bh[nfp * 2 + 0][1] = r4[1];
                bh[nfp * 2 + 1][0] = r4[2]; bh[nfp * 2 + 1][1] = r4[3];
            }
            #pragma unroll
            for (int mf = 0; mf < 4; mf++)
                #pragma unroll
                for (int nf = 0; nf < 4; nf++)
                    mma_f16(acc[mf][nf], ah[mf], bh[nf]);
        }
    }

    // epilogue: 64 rows x warp's 32 cols, + bias3 (residual folded into W3)
    #pragma unroll
    for (int mf = 0; mf < 4; mf++) {
        #pragma unroll
        for (int hf = 0; hf < 2; hf++) {
            int r = mf * 16 + hf * 8 + (lane >> 2);
            int mrow = mt * 64 + r;
            float bv = bias[b * C_ + mrow];
            long base = ((long)b * C_ + mrow) * N_ + (long)nt * 256;
            float* dst = outO + base;
            #pragma unroll
            for (int nf = 0; nf < 4; nf++) {
                int n = wn + nf * 8 + 2 * (lane & 3);
                float2 o;
                o.x = acc[mf][nf][hf * 2 + 0] + bv;
                o.y = acc[mf][nf][hf * 2 + 1] + bv;
                *(float2*)&dst[n] = o;
            }
        }
    }
}

// ============================================================
// host launch
// ============================================================
extern "C" void kernel_launch(void* const* d_in, const int* in_sizes, int n_in,
                              void* d_out, int out_size) {
    const float* x    = (const float*)d_in[0];
    const float* gnw  = (const float*)d_in[1];
    const float* gnb  = (const float*)d_in[2];
    const float* qkvW = (const float*)d_in[3];
    const float* ow   = (const float*)d_in[4];
    const float* ob   = (const float*)d_in[5];
    float* out = (float*)d_out;

    float* pBias3;
    __half *pXT, *pW3;
    cudaGetSymbolAddress((void**)&pBias3, d_bias3);
    cudaGetSymbolAddress((void**)&pXT, d_xT);
    cudaGetSymbolAddress((void**)&pW3, d_W3);

    cudaFuncSetAttribute(kv_sim, cudaFuncAttributeMaxDynamicSharedMemorySize, KV_SMEM);
    cudaFuncSetAttribute(gemm_out, cudaFuncAttributeMaxDynamicSharedMemorySize, KV_SMEM);

    tconv_stats<<<dim3(1024, 4, 4), dim3(32, 8)>>>(x, pXT);
    gn_stats2<<<16, 256>>>(gnw, gnb);
    build_wp<<<dim3(768, 4), 256>>>(qkvW);

    kv_sim<<<dim3(8, 128, 4), 256, KV_SMEM>>>();
    sim_part2<<<dim3(32, 8), 1024>>>();
    sim_final<<<32, 1024>>>();
    build_w23<<<dim3(256, 4), 256>>>(ow, ob);

    gemm_out<<<dim3(4, 128, 4), 256, KV_SMEM>>>(pW3, pXT, pBias3, out);
}